// round 2
// baseline (speedup 1.0000x reference)
#include <cuda_runtime.h>
#include <cuda_bf16.h>

#define HN 128
#define FF 256
#define TM 128
#define NMAX 50048
#define EMAX 800000
#define EPS 1e-5f

// ---------------- static scratch (no allocation) ----------------
__device__ float g_P[(size_t)NMAX * FF];         // P = node_emb @ W_top + b1
__device__ float g_h[(size_t)EMAX * FF];         // pre-BN linear output per edge
__device__ float g_agg[(size_t)NMAX * HN];       // segment sum
__device__ float g_stats1[2 * FF];
__device__ float g_stats2[2 * HN];
__device__ float g_scale[FF];
__device__ float g_shift[FF];
__device__ int   g_is64;

// ---------------- helpers ----------------
__device__ __forceinline__ float sigmoidf_(float x) {
    return __fdividef(1.f, 1.f + __expf(-x));
}
__device__ __forceinline__ float tanhf_(float x) {
    float t = __expf(2.f * x);                 // +inf -> 1, 0 -> -1, no NaN in our range
    return 1.f - __fdividef(2.f, t + 1.f);
}
__device__ __forceinline__ long long load_index(const void* p, long long e) {
    if (g_is64) return ((const long long*)p)[e];
    return (long long)((const int*)p)[e];
}

// ---------------- index dtype detection ----------------
// If indices are int64 (values < 2^31), every odd 32-bit word of the first 64
// entries is zero. 64 random int32 indices in [0,50000) all being zero has
// probability ~0. Deterministic given fixed inputs.
__global__ void detect_kernel(const unsigned* __restrict__ u) {
    unsigned v = 0;
    for (int k = threadIdx.x; k < 64; k += 32) v |= u[2 * k + 1];
#pragma unroll
    for (int o = 16; o; o >>= 1) v |= __shfl_xor_sync(0xffffffffu, v, o);
    if (threadIdx.x == 0) g_is64 = (v == 0) ? 1 : 0;
}

__global__ void zero_kernel(int aggCount) {
    const int stride = gridDim.x * blockDim.x;
    const int t0 = blockIdx.x * blockDim.x + threadIdx.x;
    for (int j = t0; j < aggCount; j += stride) g_agg[j] = 0.f;
    if (t0 < 2 * FF) g_stats1[t0] = 0.f;
    if (t0 < 2 * HN) g_stats2[t0] = 0.f;
}

// ---------------- tiled fp32 GEMM ----------------
// MODE 0:  out = A @ W1[0:128,:]   + b1          (A = node_emb,  M = N)
// MODE 1:  out = A @ W1[128:256,:] + g_P[i[row]] (A = edge_emb,  M = E)
// CTA tile: 128 rows x 256 cols. 256 threads, each owns 8 rows x 16 cols.
// Column fragment of thread (tr,tc): cols { tc*4 + m + 64*q : m<4, q<4 } (conflict-free LDS.128).
#define ASTRIDE 130
template <int MODE>
__global__ __launch_bounds__(256) void gemm_kernel(
    const float* __restrict__ A, const float* __restrict__ W1,
    const float* __restrict__ b1, const void* __restrict__ ibuf,
    float* __restrict__ out, int M)
{
    extern __shared__ float sm[];
    float* As = sm;                       // [128][ASTRIDE]
    float* Bs = sm + TM * ASTRIDE;        // [128][256]

    const int tid = threadIdx.x;
    const int tr = tid >> 4;              // 0..15
    const int tc = tid & 15;              // 0..15
    const long long base = (long long)blockIdx.x * TM;

    // W tile (128x256) straight copy, float4 both sides
    const float* Wsrc = W1 + (MODE == 1 ? HN * FF : 0);
    for (int w = tid * 4; w < HN * FF; w += 256 * 4)
        *(float4*)(Bs + w) = *(const float4*)(Wsrc + w);

    // A tile (128x128) row-major with pad-2 stride (scalar stores)
    for (int off = tid * 4; off < TM * HN; off += 256 * 4) {
        const int row = off >> 7, k = off & 127;
        float4 v = make_float4(0.f, 0.f, 0.f, 0.f);
        const long long grow = base + row;
        if (grow < M) v = *(const float4*)(A + grow * HN + k);
        float* dst = As + row * ASTRIDE + k;
        dst[0] = v.x; dst[1] = v.y; dst[2] = v.z; dst[3] = v.w;
    }
    __syncthreads();

    float acc[8][16];
#pragma unroll
    for (int j = 0; j < 8; j++)
#pragma unroll
        for (int c = 0; c < 16; c++) acc[j][c] = 0.f;

    const float* arow = As + (tr * 8) * ASTRIDE;
#pragma unroll 2
    for (int k = 0; k < HN; k++) {
        float a[8], b[16];
#pragma unroll
        for (int j = 0; j < 8; j++) a[j] = arow[j * ASTRIDE + k];
#pragma unroll
        for (int q = 0; q < 4; q++) {
            const float4 bv = *(const float4*)(Bs + k * FF + tc * 4 + 64 * q);
            b[q * 4 + 0] = bv.x; b[q * 4 + 1] = bv.y;
            b[q * 4 + 2] = bv.z; b[q * 4 + 3] = bv.w;
        }
#pragma unroll
        for (int j = 0; j < 8; j++)
#pragma unroll
            for (int c = 0; c < 16; c++)
                acc[j][c] = fmaf(a[j], b[c], acc[j][c]);
    }

    // epilogue
#pragma unroll
    for (int j = 0; j < 8; j++) {
        const long long row = base + tr * 8 + j;
        if (row >= M) continue;
        long long prow = 0;
        if (MODE == 1) prow = load_index(ibuf, row);
#pragma unroll
        for (int q = 0; q < 4; q++) {
            const int col = tc * 4 + 64 * q;
            float4 r;
            r.x = acc[j][q * 4 + 0]; r.y = acc[j][q * 4 + 1];
            r.z = acc[j][q * 4 + 2]; r.w = acc[j][q * 4 + 3];
            if (MODE == 0) {
                const float4 bb = *(const float4*)(b1 + col);
                r.x += bb.x; r.y += bb.y; r.z += bb.z; r.w += bb.w;
            } else {
                const float4 p = *(const float4*)(g_P + prow * FF + col);
                r.x += p.x; r.y += p.y; r.z += p.z; r.w += p.w;
            }
            *(float4*)(out + row * FF + col) = r;
        }
    }
}

// ---------------- BN1 stats over g_h ----------------
__global__ void stats1_kernel(int E) {
    const int t = blockIdx.x * blockDim.x + threadIdx.x;
    const int col = t & (FF - 1);
    const int r0 = t >> 8;
    const int rs = (gridDim.x * blockDim.x) >> 8;
    float s = 0.f, sq = 0.f;
    for (long long r = r0; r < E; r += rs) {
        const float v = g_h[r * FF + col];
        s += v; sq = fmaf(v, v, sq);
    }
    atomicAdd(&g_stats1[col], s);
    atomicAdd(&g_stats1[FF + col], sq);
}

__global__ void finalize1_kernel(const float* __restrict__ gamma1,
                                 const float* __restrict__ beta1, float invE) {
    const int j = threadIdx.x;   // 256
    const float mu  = g_stats1[j] * invE;
    const float var = g_stats1[FF + j] * invE - mu * mu;
    const float s   = gamma1[j] * rsqrtf(var + EPS);
    g_scale[j] = s;
    g_shift[j] = beta1[j] - mu * s;
}

// ---------------- gate + scatter-add ----------------
__global__ void gate_scatter_kernel(const void* __restrict__ ibuf, int E) {
    const long long total  = (long long)E * HN;
    const long long stride = (long long)gridDim.x * blockDim.x;
    for (long long t = (long long)blockIdx.x * blockDim.x + threadIdx.x;
         t < total; t += stride) {
        const long long e = t >> 7;
        const int c = (int)(t & (HN - 1));
        const float hf = g_h[e * FF + c]      * g_scale[c]      + g_shift[c];
        const float hc = g_h[e * FF + HN + c] * g_scale[HN + c] + g_shift[HN + c];
        const float msg = sigmoidf_(hf) * tanhf_(hc);
        const long long idx = load_index(ibuf, e);
        atomicAdd(g_agg + idx * HN + c, msg);
    }
}

// ---------------- BN2 stats over g_agg ----------------
__global__ void stats2_kernel(int N) {
    const int t = blockIdx.x * blockDim.x + threadIdx.x;
    const int col = t & (HN - 1);
    const int r0 = t >> 7;
    const int rs = (gridDim.x * blockDim.x) >> 7;
    float s = 0.f, sq = 0.f;
    for (long long r = r0; r < N; r += rs) {
        const float v = g_agg[r * HN + col];
        s += v; sq = fmaf(v, v, sq);
    }
    atomicAdd(&g_stats2[col], s);
    atomicAdd(&g_stats2[HN + col], sq);
}

// ---------------- final: out = tanh(node_emb + BN2(agg)) ----------------
__global__ void final_kernel(const float* __restrict__ node_emb,
                             const float* __restrict__ gamma2,
                             const float* __restrict__ beta2,
                             float* __restrict__ out, int total, float invN) {
    const int t = blockIdx.x * blockDim.x + threadIdx.x;
    if (t >= total) return;
    const int col = t & (HN - 1);
    const float mu  = g_stats2[col] * invN;
    const float var = g_stats2[HN + col] * invN - mu * mu;
    const float c1  = (g_agg[t] - mu) * rsqrtf(var + EPS) * gamma2[col] + beta2[col];
    out[t] = tanhf_(node_emb[t] + c1);
}

// ---------------- launch ----------------
extern "C" void kernel_launch(void* const* d_in, const int* in_sizes, int n_in,
                              void* d_out, int out_size) {
    const float* node_emb = (const float*)d_in[0];
    const float* edge_emb = (const float*)d_in[1];
    const void*  ibuf     = d_in[2];
    const float* W1       = (const float*)d_in[3];
    const float* b1       = (const float*)d_in[4];
    const float* gamma1   = (const float*)d_in[5];
    const float* beta1    = (const float*)d_in[6];
    const float* gamma2   = (const float*)d_in[7];
    const float* beta2    = (const float*)d_in[8];
    float* out = (float*)d_out;

    const int N = in_sizes[0] / HN;
    const int E = in_sizes[1] / HN;

    const int smem = (TM * ASTRIDE + HN * FF) * (int)sizeof(float);
    static bool attr_done = false;
    if (!attr_done) {
        cudaFuncSetAttribute(gemm_kernel<0>, cudaFuncAttributeMaxDynamicSharedMemorySize, smem);
        cudaFuncSetAttribute(gemm_kernel<1>, cudaFuncAttributeMaxDynamicSharedMemorySize, smem);
        attr_done = true;
    }

    float* g_P_ptr;   cudaGetSymbolAddress((void**)&g_P_ptr, g_P);
    float* g_h_ptr;   cudaGetSymbolAddress((void**)&g_h_ptr, g_h);

    detect_kernel<<<1, 32>>>((const unsigned*)ibuf);
    zero_kernel<<<4096, 256>>>(N * HN);

    const int gridP = (N + TM - 1) / TM;
    gemm_kernel<0><<<gridP, 256, smem>>>(node_emb, W1, b1, ibuf, g_P_ptr, N);

    const int gridA = (E + TM - 1) / TM;
    gemm_kernel<1><<<gridA, 256, smem>>>(edge_emb, W1, b1, ibuf, g_h_ptr, E);

    stats1_kernel<<<2048, 256>>>(E);
    finalize1_kernel<<<1, 256>>>(gamma1, beta1, 1.0f / (float)E);

    gate_scatter_kernel<<<4096, 256>>>(ibuf, E);

    stats2_kernel<<<1024, 256>>>(N);
    final_kernel<<<(N * HN + 255) / 256, 256>>>(node_emb, gamma2, beta2, out,
                                                N * HN, 1.0f / (float)N);
}

// round 4
// speedup vs baseline: 1.7456x; 1.7456x over previous
#include <cuda_runtime.h>
#include <cstdint>

#define HN 128
#define FF 256
#define NMAX 50048
#define EMAX 800000
#define EPS 1e-5f

// ---------------- static scratch ----------------
__device__ float g_P[(size_t)NMAX * FF];
__device__ float g_h[(size_t)EMAX * FF];
__device__ float g_agg[(size_t)NMAX * HN];
__device__ float g_Wt[2][FF * HN];          // W^T tf32-rounded, n-major
__device__ float g_stats1[2 * FF];
__device__ float g_stats2[2 * HN];
__device__ float g_scale[FF];
__device__ float g_shift[FF];
__device__ int   g_is64;

// ---------------- helpers ----------------
__device__ __forceinline__ uint32_t smem_u32(const void* p) {
    uint32_t a;
    asm("{ .reg .u64 t; cvta.to.shared.u64 t, %1; cvt.u32.u64 %0, t; }" : "=r"(a) : "l"(p));
    return a;
}
__device__ __forceinline__ float tf32r(float x) {
    float y; asm("cvt.rna.tf32.f32 %0, %1;" : "=f"(y) : "f"(x)); return y;
}
__device__ __forceinline__ float sigmoidf_(float x) {
    return __fdividef(1.f, 1.f + __expf(-x));
}
__device__ __forceinline__ float tanhf_(float x) {
    float t = __expf(2.f * x);
    return 1.f - __fdividef(2.f, t + 1.f);
}
__device__ __forceinline__ void cpasync16(uint32_t dst, const void* src, bool pred) {
    int sz = pred ? 16 : 0;
    asm volatile("cp.async.cg.shared.global [%0], [%1], 16, %2;"
                 :: "r"(dst), "l"(src), "r"(sz) : "memory");
}
#define CP_COMMIT() asm volatile("cp.async.commit_group;" ::: "memory")
#define CP_WAIT1()  asm volatile("cp.async.wait_group 1;" ::: "memory")

__device__ __forceinline__ void mma8(float* c, const uint32_t* a, const uint32_t* b) {
    asm volatile("mma.sync.aligned.m16n8k8.row.col.f32.tf32.tf32.f32 "
                 "{%0,%1,%2,%3}, {%4,%5,%6,%7}, {%8,%9}, {%0,%1,%2,%3};"
                 : "+f"(c[0]), "+f"(c[1]), "+f"(c[2]), "+f"(c[3])
                 : "r"(a[0]), "r"(a[1]), "r"(a[2]), "r"(a[3]), "r"(b[0]), "r"(b[1]));
}

// SMEM map (bytes)
#define AS_STRIDE 68
#define BS_STRIDE 132
#define BS_OFF    0
#define AS_OFF    135168               // 256*132*4
#define AS_SZ     34816                // 128*68*4
#define SSTAT_OFF 204800               // AS_OFF + 2*AS_SZ
#define SMEM_SZ   206848               // + 512*4

// ---------------- small kernels ----------------
__global__ void detect_kernel(const unsigned* __restrict__ u) {
    unsigned v = 0;
    for (int k = threadIdx.x; k < 64; k += 32) v |= u[2 * k + 1];
#pragma unroll
    for (int o = 16; o; o >>= 1) v |= __shfl_xor_sync(0xffffffffu, v, o);
    if (threadIdx.x == 0) g_is64 = (v == 0) ? 1 : 0;
}

__global__ void zero_kernel(int aggCount) {
    const int stride = gridDim.x * blockDim.x;
    const int t0 = blockIdx.x * blockDim.x + threadIdx.x;
    for (int j = t0; j < aggCount; j += stride) g_agg[j] = 0.f;
    if (t0 < 2 * FF) g_stats1[t0] = 0.f;
    if (t0 < 2 * HN) g_stats2[t0] = 0.f;
}

__global__ void prepW_kernel(const float* __restrict__ W1) {
    const int t = blockIdx.x * blockDim.x + threadIdx.x;
    if (t >= FF * HN) return;
    const int n = t >> 7, k = t & 127;
    g_Wt[0][n * HN + k] = tf32r(W1[k * FF + n]);
    g_Wt[1][n * HN + k] = tf32r(W1[(HN + k) * FF + n]);
}

// ---------------- warp-mma TF32 GEMM ----------------
// MODE 0: g_P = node_emb @ W_top + b1                 (M = N_nodes)
// MODE 1: g_h = edge_emb @ W_bot + g_P[i[row]]  (+ fused BN1 column stats)
template <int MODE>
__global__ void __launch_bounds__(256, 1) mma_gemm(
    const float* __restrict__ A, const float* __restrict__ b1,
    const void* __restrict__ ibuf, float* __restrict__ out, int M)
{
    extern __shared__ char smem[];
    float* Bs = (float*)(smem + BS_OFF);
    float* As0 = (float*)(smem + AS_OFF);
    float* As1 = (float*)(smem + AS_OFF + AS_SZ);
    float* sstat = (float*)(smem + SSTAT_OFF);
    const uint32_t as_u0 = smem_u32(As0);
    const uint32_t as_u1 = smem_u32(As1);

    const int tid = threadIdx.x, lane = tid & 31, wid = tid >> 5;
    const int wm = wid & 1, wn = wid >> 1;
    const int ntiles = (M + 127) >> 7;
    const int grid = gridDim.x;
    const int is64 = (MODE == 1) ? g_is64 : 0;

    // B tile (W^T): [n][k] pad-132, conflict-free frag loads
    for (int i = tid; i < 8192; i += 256) {
        const int n = i >> 5, k4 = (i & 31) << 2;
        *(float4*)(Bs + n * BS_STRIDE + k4) = *(const float4*)(g_Wt[MODE] + n * HN + k4);
    }
    if (MODE == 1) { sstat[tid] = 0.f; sstat[tid + 256] = 0.f; }
    __syncthreads();

    float acc[4][8][4];
#pragma unroll
    for (int mt = 0; mt < 4; mt++)
#pragma unroll
        for (int nt = 0; nt < 8; nt++)
#pragma unroll
            for (int r = 0; r < 4; r++) acc[mt][nt][r] = 0.f;

    auto prefetch = [&](int tile, int kc, int b) {
        const long long rbase = (long long)tile << 7;
        const uint32_t au = b ? as_u1 : as_u0;
#pragma unroll
        for (int s = 0; s < 8; s++) {
            const int j = tid + s * 256;         // 0..2047
            const int r = j >> 4, kq = (j & 15) << 2;
            const uint32_t dst = au + (uint32_t)(r * AS_STRIDE + kq) * 4u;
            const float* src = A + (rbase + r) * HN + kc * 64 + kq;
            cpasync16(dst, src, rbase + r < (long long)M);
        }
    };

    auto compute = [&](int b, int kc) {
        const float* as = b ? As1 : As0;
        const float* bsc = Bs + kc * 64;
#pragma unroll
        for (int ks = 0; ks < 8; ks++) {
            uint32_t a[4][4], bb[8][2];
            const int ka = ks * 8 + (lane & 3);
#pragma unroll
            for (int mt = 0; mt < 4; mt++) {
                const uint32_t* p = (const uint32_t*)(as + (wm * 64 + mt * 16 + (lane >> 2)) * AS_STRIDE + ka);
                a[mt][0] = p[0];
                a[mt][2] = p[4];
                a[mt][1] = p[8 * AS_STRIDE];
                a[mt][3] = p[8 * AS_STRIDE + 4];
            }
#pragma unroll
            for (int nt = 0; nt < 8; nt++) {
                const uint32_t* p = (const uint32_t*)(bsc + (wn * 64 + nt * 8 + (lane >> 2)) * BS_STRIDE + ka);
                bb[nt][0] = p[0];
                bb[nt][1] = p[4];
            }
#pragma unroll
            for (int mt = 0; mt < 4; mt++)
#pragma unroll
                for (int nt = 0; nt < 8; nt++)
                    mma8(acc[mt][nt], a[mt], bb[nt]);
        }
    };

    auto epilogue = [&](int tile) {
        const long long rbase = (long long)tile << 7;
        float s[8][2], q[8][2];
        if (MODE == 1) {
#pragma unroll
            for (int nt = 0; nt < 8; nt++) {
                s[nt][0] = s[nt][1] = 0.f; q[nt][0] = q[nt][1] = 0.f;
            }
        }
#pragma unroll
        for (int mt = 0; mt < 4; mt++) {
            long long pb[2]; bool valid[2]; float* orow[2];
#pragma unroll
            for (int h = 0; h < 2; h++) {
                const long long row = rbase + wm * 64 + mt * 16 + (lane >> 2) + h * 8;
                valid[h] = row < (long long)M;
                orow[h] = out + row * FF;
                pb[h] = 0;
                if (MODE == 1 && valid[h]) {
                    const long long idx = is64 ? ((const long long*)ibuf)[row]
                                               : (long long)((const int*)ibuf)[row];
                    pb[h] = idx * FF;
                }
            }
#pragma unroll
            for (int nt = 0; nt < 8; nt++) {
                const int c0 = wn * 64 + nt * 8 + 2 * (lane & 3);
#pragma unroll
                for (int h = 0; h < 2; h++) {
                    if (!valid[h]) continue;
                    float2 add;
                    if (MODE == 0) add = *(const float2*)(b1 + c0);
                    else           add = *(const float2*)(g_P + pb[h] + c0);
                    float2 o;
                    o.x = acc[mt][nt][2 * h] + add.x;
                    o.y = acc[mt][nt][2 * h + 1] + add.y;
                    *(float2*)(orow[h] + c0) = o;
                    if (MODE == 1) {
                        s[nt][0] += o.x; q[nt][0] = fmaf(o.x, o.x, q[nt][0]);
                        s[nt][1] += o.y; q[nt][1] = fmaf(o.y, o.y, q[nt][1]);
                    }
                }
                acc[mt][nt][0] = 0.f; acc[mt][nt][1] = 0.f;
                acc[mt][nt][2] = 0.f; acc[mt][nt][3] = 0.f;
            }
        }
        if (MODE == 1) {
#pragma unroll
            for (int o = 4; o < 32; o <<= 1) {
#pragma unroll
                for (int nt = 0; nt < 8; nt++) {
                    s[nt][0] += __shfl_xor_sync(0xffffffffu, s[nt][0], o);
                    s[nt][1] += __shfl_xor_sync(0xffffffffu, s[nt][1], o);
                    q[nt][0] += __shfl_xor_sync(0xffffffffu, q[nt][0], o);
                    q[nt][1] += __shfl_xor_sync(0xffffffffu, q[nt][1], o);
                }
            }
            if (lane < 4) {
#pragma unroll
                for (int nt = 0; nt < 8; nt++) {
                    const int c0 = wn * 64 + nt * 8 + 2 * lane;
                    atomicAdd(&sstat[c0], s[nt][0]);
                    atomicAdd(&sstat[c0 + 1], s[nt][1]);
                    atomicAdd(&sstat[256 + c0], q[nt][0]);
                    atomicAdd(&sstat[256 + c0 + 1], q[nt][1]);
                }
            }
        }
    };

    const int rem = ntiles - (int)blockIdx.x;
    const int nIter = rem > 0 ? (rem + grid - 1) / grid : 0;

    if (nIter > 0) {
        prefetch(blockIdx.x, 0, 0); CP_COMMIT();
        prefetch(blockIdx.x, 1, 1); CP_COMMIT();
        int buf = 0;
        for (int it = 0; it < nIter; it++) {
            const int tile = blockIdx.x + it * grid;
            const int tnext = tile + grid;
            // chunk 0
            CP_WAIT1(); __syncthreads();
            compute(buf, 0);
            __syncthreads();
            if (tnext < ntiles) prefetch(tnext, 0, buf);
            CP_COMMIT();
            buf ^= 1;
            // chunk 1
            CP_WAIT1(); __syncthreads();
            compute(buf, 1);
            __syncthreads();
            if (tnext < ntiles) prefetch(tnext, 1, buf);
            CP_COMMIT();
            buf ^= 1;
            epilogue(tile);
        }
    }
    __syncthreads();
    if (MODE == 1) {
        for (int j = tid; j < 512; j += 256) atomicAdd(&g_stats1[j], sstat[j]);
    }
}

// ---------------- BN1 finalize ----------------
__global__ void finalize1_kernel(const float* __restrict__ gamma1,
                                 const float* __restrict__ beta1, float invE) {
    const int j = threadIdx.x;
    const float mu  = g_stats1[j] * invE;
    const float var = g_stats1[FF + j] * invE - mu * mu;
    const float s   = gamma1[j] * rsqrtf(var + EPS);
    g_scale[j] = s;
    g_shift[j] = beta1[j] - mu * s;
}

// ---------------- gate + scatter (vector atomics) ----------------
__global__ void gate_scatter_kernel(const void* __restrict__ ibuf, int E) {
    __shared__ float ssc[FF], ssh[FF];
    ssc[threadIdx.x] = g_scale[threadIdx.x];
    ssh[threadIdx.x] = g_shift[threadIdx.x];
    __syncthreads();
    const int is64 = g_is64;
    const long long total  = (long long)E * 32;
    const long long stride = (long long)gridDim.x * blockDim.x;
    for (long long t = (long long)blockIdx.x * blockDim.x + threadIdx.x;
         t < total; t += stride) {
        const long long e = t >> 5;
        const int c4 = (int)(t & 31) << 2;
        const float4 f = *(const float4*)(g_h + e * FF + c4);
        const float4 g = *(const float4*)(g_h + e * FF + HN + c4);
        float4 m;
        m.x = sigmoidf_(f.x * ssc[c4 + 0] + ssh[c4 + 0]) * tanhf_(g.x * ssc[HN + c4 + 0] + ssh[HN + c4 + 0]);
        m.y = sigmoidf_(f.y * ssc[c4 + 1] + ssh[c4 + 1]) * tanhf_(g.y * ssc[HN + c4 + 1] + ssh[HN + c4 + 1]);
        m.z = sigmoidf_(f.z * ssc[c4 + 2] + ssh[c4 + 2]) * tanhf_(g.z * ssc[HN + c4 + 2] + ssh[HN + c4 + 2]);
        m.w = sigmoidf_(f.w * ssc[c4 + 3] + ssh[c4 + 3]) * tanhf_(g.w * ssc[HN + c4 + 3] + ssh[HN + c4 + 3]);
        const long long idx = is64 ? ((const long long*)ibuf)[e]
                                   : (long long)((const int*)ibuf)[e];
        float* dst = g_agg + idx * HN + c4;
        asm volatile("red.global.add.v4.f32 [%0], {%1, %2, %3, %4};"
                     :: "l"(dst), "f"(m.x), "f"(m.y), "f"(m.z), "f"(m.w) : "memory");
    }
}

// ---------------- BN2 + final ----------------
__global__ void stats2_kernel(int N) {
    const int t = blockIdx.x * blockDim.x + threadIdx.x;
    const int col = t & (HN - 1);
    const int r0 = t >> 7;
    const int rs = (gridDim.x * blockDim.x) >> 7;
    float s = 0.f, sq = 0.f;
    for (long long r = r0; r < N; r += rs) {
        const float v = g_agg[r * HN + col];
        s += v; sq = fmaf(v, v, sq);
    }
    atomicAdd(&g_stats2[col], s);
    atomicAdd(&g_stats2[HN + col], sq);
}

__global__ void final_kernel(const float* __restrict__ node_emb,
                             const float* __restrict__ gamma2,
                             const float* __restrict__ beta2,
                             float* __restrict__ out, int total, float invN) {
    const int t = blockIdx.x * blockDim.x + threadIdx.x;
    if (t >= total) return;
    const int col = t & (HN - 1);
    const float mu  = g_stats2[col] * invN;
    const float var = g_stats2[HN + col] * invN - mu * mu;
    const float c1  = (g_agg[t] - mu) * rsqrtf(var + EPS) * gamma2[col] + beta2[col];
    out[t] = tanhf_(node_emb[t] + c1);
}

// ---------------- launch ----------------
extern "C" void kernel_launch(void* const* d_in, const int* in_sizes, int n_in,
                              void* d_out, int out_size) {
    const float* node_emb = (const float*)d_in[0];
    const float* edge_emb = (const float*)d_in[1];
    const void*  ibuf     = d_in[2];
    const float* W1       = (const float*)d_in[3];
    const float* b1       = (const float*)d_in[4];
    const float* gamma1   = (const float*)d_in[5];
    const float* beta1    = (const float*)d_in[6];
    const float* gamma2   = (const float*)d_in[7];
    const float* beta2    = (const float*)d_in[8];
    float* out = (float*)d_out;

    const int N = in_sizes[0] / HN;
    const int E = in_sizes[1] / HN;

    static bool attr_done = false;
    if (!attr_done) {
        cudaFuncSetAttribute(mma_gemm<0>, cudaFuncAttributeMaxDynamicSharedMemorySize, SMEM_SZ);
        cudaFuncSetAttribute(mma_gemm<1>, cudaFuncAttributeMaxDynamicSharedMemorySize, SMEM_SZ);
        attr_done = true;
    }

    float* g_P_ptr; cudaGetSymbolAddress((void**)&g_P_ptr, g_P);
    float* g_h_ptr; cudaGetSymbolAddress((void**)&g_h_ptr, g_h);

    detect_kernel<<<1, 32>>>((const unsigned*)ibuf);
    zero_kernel<<<4096, 256>>>(N * HN);
    prepW_kernel<<<(FF * HN + 255) / 256, 256>>>(W1);

    mma_gemm<0><<<148, 256, SMEM_SZ>>>(node_emb, b1, ibuf, g_P_ptr, N);
    mma_gemm<1><<<148, 256, SMEM_SZ>>>(edge_emb, b1, ibuf, g_h_ptr, E);

    finalize1_kernel<<<1, 256>>>(gamma1, beta1, 1.0f / (float)E);
    gate_scatter_kernel<<<8192, 256>>>(ibuf, E);

    stats2_kernel<<<1024, 256>>>(N);
    final_kernel<<<(N * HN + 255) / 256, 256>>>(node_emb, gamma2, beta2, out,
                                                N * HN, 1.0f / (float)N);
}

// round 5
// speedup vs baseline: 2.4442x; 1.4002x over previous
#include <cuda_runtime.h>
#include <cstdint>

#define HN 128
#define FF 256
#define NMAX 50048
#define EMAX 800000
#define EPS 1e-5f

// ---------------- static scratch ----------------
__device__ float g_P[(size_t)NMAX * FF];
__device__ float g_h[(size_t)EMAX * FF];
__device__ float g_agg[(size_t)NMAX * HN];
__device__ float g_Wt[2][32768];            // B prepacked in mma-frag order
__device__ float g_stats1[2 * FF];
__device__ float g_stats2[2 * HN];
__device__ float g_scale[FF];
__device__ float g_shift[FF];
__device__ int   g_is64;

// ---------------- helpers ----------------
__device__ __forceinline__ uint32_t smem_u32(const void* p) {
    uint32_t a;
    asm("{ .reg .u64 t; cvta.to.shared.u64 t, %1; cvt.u32.u64 %0, t; }" : "=r"(a) : "l"(p));
    return a;
}
__device__ __forceinline__ float tf32r(float x) {
    float y; asm("cvt.rna.tf32.f32 %0, %1;" : "=f"(y) : "f"(x)); return y;
}
__device__ __forceinline__ float sigmoidf_(float x) {
    return __fdividef(1.f, 1.f + __expf(-x));
}
__device__ __forceinline__ float tanhf_(float x) {
    float t = __expf(2.f * x);
    return 1.f - __fdividef(2.f, t + 1.f);
}
__device__ __forceinline__ void cpasync16(uint32_t dst, const void* src, bool pred) {
    int sz = pred ? 16 : 0;
    asm volatile("cp.async.cg.shared.global [%0], [%1], 16, %2;"
                 :: "r"(dst), "l"(src), "r"(sz) : "memory");
}
#define CP_COMMIT() asm volatile("cp.async.commit_group;" ::: "memory")
#define CP_WAIT1()  asm volatile("cp.async.wait_group 1;" ::: "memory")

__device__ __forceinline__ void mma8(float* c, const uint32_t* a, uint32_t b0, uint32_t b1) {
    asm volatile("mma.sync.aligned.m16n8k8.row.col.f32.tf32.tf32.f32 "
                 "{%0,%1,%2,%3}, {%4,%5,%6,%7}, {%8,%9}, {%0,%1,%2,%3};"
                 : "+f"(c[0]), "+f"(c[1]), "+f"(c[2]), "+f"(c[3])
                 : "r"(a[0]), "r"(a[1]), "r"(a[2]), "r"(a[3]), "r"(b0), "r"(b1));
}

// SMEM map (bytes)
#define AS_STRIDE 68
#define BS_OFF    0
#define BS_BYTES  131072               // 32768 floats, frag-packed
#define AS_OFF    131072
#define AS_SZ     34816                // 128*68*4
#define SSTAT_OFF 200704               // AS_OFF + 2*AS_SZ
#define SMEM_SZ   202752               // + 512*4

// ---------------- small kernels ----------------
__global__ void detect_kernel(const unsigned* __restrict__ u) {
    unsigned v = 0;
    for (int k = threadIdx.x; k < 64; k += 32) v |= u[2 * k + 1];
#pragma unroll
    for (int o = 16; o; o >>= 1) v |= __shfl_xor_sync(0xffffffffu, v, o);
    if (threadIdx.x == 0) g_is64 = (v == 0) ? 1 : 0;
}

__global__ void zero_kernel(int aggCount) {
    const int stride = gridDim.x * blockDim.x;
    const int t0 = blockIdx.x * blockDim.x + threadIdx.x;
    for (int j = t0; j < aggCount; j += stride) g_agg[j] = 0.f;
    if (t0 < 2 * FF) g_stats1[t0] = 0.f;
    if (t0 < 2 * HN) g_stats2[t0] = 0.f;
}

// B prepack: g_Wt[mode][ ((wn*8+kpair)*4 + nt)*128 + lane*4 + r ]
//   ks = kpair*2 + (r>>1), j = r&1
//   k  = ks*8 + (lane&3) + j*4        (0..127)
//   n  = wn*32 + nt*8 + (lane>>2)     (0..255)
//   val = tf32(W1[(k + mode*128)*FF + n])
__global__ void prepW_kernel(const float* __restrict__ W1) {
    const int gid = blockIdx.x * blockDim.x + threadIdx.x;
    if (gid >= 65536) return;
    const int mode = gid >> 15;
    const int u = gid & 32767;
    const int r = u & 3, lane = (u >> 2) & 31, nt = (u >> 7) & 3;
    const int kpw = u >> 9, wn = kpw >> 3, kpair = kpw & 7;
    const int ks = kpair * 2 + (r >> 1), j = r & 1;
    const int k = ks * 8 + (lane & 3) + j * 4;
    const int n = wn * 32 + nt * 8 + (lane >> 2);
    g_Wt[mode][u] = tf32r(W1[(k + mode * HN) * FF + n]);
}

// ---------------- warp-mma TF32 GEMM (16 warps) ----------------
// MODE 0: g_P = node_emb @ W_top + b1
// MODE 1: g_h = edge_emb @ W_bot + g_P[i[row]]  (+ fused BN1 stats)
// Warp (wm = wid&1, wn = wid>>1) owns rows wm*64+[0,64), cols wn*32+[0,32).
template <int MODE>
__global__ void __launch_bounds__(512, 1) mma_gemm(
    const float* __restrict__ A, const float* __restrict__ b1,
    const void* __restrict__ ibuf, float* __restrict__ out, int M)
{
    extern __shared__ char smem[];
    float* Bs  = (float*)(smem + BS_OFF);
    float* As0 = (float*)(smem + AS_OFF);
    float* As1 = (float*)(smem + AS_OFF + AS_SZ);
    float* sstat = (float*)(smem + SSTAT_OFF);
    const uint32_t as_u0 = smem_u32(As0);
    const uint32_t as_u1 = smem_u32(As1);

    const int tid = threadIdx.x, lane = tid & 31, wid = tid >> 5;
    const int wm = wid & 1, wn = wid >> 1;
    const int ntiles = (M + 127) >> 7;
    const int grid = gridDim.x;
    const int is64 = (MODE == 1) ? g_is64 : 0;

    // B (frag-packed) straight copy: 32768 floats
    for (int i = tid * 4; i < 32768; i += 512 * 4)
        *(float4*)(Bs + i) = *(const float4*)(g_Wt[MODE] + i);
    if (MODE == 1) sstat[tid] = 0.f;
    __syncthreads();

    float acc[4][4][4];
#pragma unroll
    for (int mt = 0; mt < 4; mt++)
#pragma unroll
        for (int nt = 0; nt < 4; nt++)
#pragma unroll
            for (int r = 0; r < 4; r++) acc[mt][nt][r] = 0.f;

    auto prefetch = [&](int tile, int kc, int b) {
        const long long rbase = (long long)tile << 7;
        const uint32_t au = b ? as_u1 : as_u0;
#pragma unroll
        for (int s = 0; s < 4; s++) {
            const int j = tid + s * 512;         // 0..2047
            const int r = j >> 4, kq = (j & 15) << 2;
            const uint32_t dst = au + (uint32_t)(r * AS_STRIDE + kq) * 4u;
            const float* src = A + (rbase + r) * HN + kc * 64 + kq;
            cpasync16(dst, src, rbase + r < (long long)M);
        }
    };

    auto compute = [&](int b, int kc) {
        const float* as = b ? As1 : As0;
        const float* bbase = Bs + (wn * 8 + kc * 4) * 512;   // (..)*4*128 floats
#pragma unroll
        for (int kp = 0; kp < 4; kp++) {
            float4 bp[4];
#pragma unroll
            for (int nt = 0; nt < 4; nt++)
                bp[nt] = *(const float4*)(bbase + (kp * 4 + nt) * 128 + lane * 4);
#pragma unroll
            for (int sub = 0; sub < 2; sub++) {
                const int ka = (kp * 2 + sub) * 8 + (lane & 3);
                uint32_t a[4][4];
#pragma unroll
                for (int mt = 0; mt < 4; mt++) {
                    const uint32_t* p = (const uint32_t*)(as + (wm * 64 + mt * 16 + (lane >> 2)) * AS_STRIDE + ka);
                    a[mt][0] = p[0];
                    a[mt][2] = p[4];
                    a[mt][1] = p[8 * AS_STRIDE];
                    a[mt][3] = p[8 * AS_STRIDE + 4];
                }
#pragma unroll
                for (int mt = 0; mt < 4; mt++)
#pragma unroll
                    for (int nt = 0; nt < 4; nt++) {
                        const uint32_t b0 = sub ? __float_as_uint(bp[nt].z) : __float_as_uint(bp[nt].x);
                        const uint32_t b1r = sub ? __float_as_uint(bp[nt].w) : __float_as_uint(bp[nt].y);
                        mma8(acc[mt][nt], a[mt], b0, b1r);
                    }
            }
        }
    };

    auto epilogue = [&](int tile) {
        const long long rbase = (long long)tile << 7;
        float s[4][2], q[4][2];
        if (MODE == 1) {
#pragma unroll
            for (int nt = 0; nt < 4; nt++) {
                s[nt][0] = s[nt][1] = 0.f; q[nt][0] = q[nt][1] = 0.f;
            }
        }
#pragma unroll
        for (int mt = 0; mt < 4; mt++) {
            long long pb[2]; bool valid[2]; float* orow[2];
#pragma unroll
            for (int h = 0; h < 2; h++) {
                const long long row = rbase + wm * 64 + mt * 16 + (lane >> 2) + h * 8;
                valid[h] = row < (long long)M;
                orow[h] = out + row * FF;
                pb[h] = 0;
                if (MODE == 1 && valid[h]) {
                    const long long idx = is64 ? ((const long long*)ibuf)[row]
                                               : (long long)((const int*)ibuf)[row];
                    pb[h] = idx * FF;
                }
            }
#pragma unroll
            for (int nt = 0; nt < 4; nt++) {
                const int c0 = wn * 32 + nt * 8 + 2 * (lane & 3);
#pragma unroll
                for (int h = 0; h < 2; h++) {
                    if (!valid[h]) continue;
                    float2 add;
                    if (MODE == 0) add = *(const float2*)(b1 + c0);
                    else           add = *(const float2*)(g_P + pb[h] + c0);
                    float2 o;
                    o.x = acc[mt][nt][2 * h] + add.x;
                    o.y = acc[mt][nt][2 * h + 1] + add.y;
                    *(float2*)(orow[h] + c0) = o;
                    if (MODE == 1) {
                        s[nt][0] += o.x; q[nt][0] = fmaf(o.x, o.x, q[nt][0]);
                        s[nt][1] += o.y; q[nt][1] = fmaf(o.y, o.y, q[nt][1]);
                    }
                }
                acc[mt][nt][0] = 0.f; acc[mt][nt][1] = 0.f;
                acc[mt][nt][2] = 0.f; acc[mt][nt][3] = 0.f;
            }
        }
        if (MODE == 1) {
#pragma unroll
            for (int o = 4; o < 32; o <<= 1) {
#pragma unroll
                for (int nt = 0; nt < 4; nt++) {
                    s[nt][0] += __shfl_xor_sync(0xffffffffu, s[nt][0], o);
                    s[nt][1] += __shfl_xor_sync(0xffffffffu, s[nt][1], o);
                    q[nt][0] += __shfl_xor_sync(0xffffffffu, q[nt][0], o);
                    q[nt][1] += __shfl_xor_sync(0xffffffffu, q[nt][1], o);
                }
            }
            if (lane < 4) {
#pragma unroll
                for (int nt = 0; nt < 4; nt++) {
                    const int c0 = wn * 32 + nt * 8 + 2 * lane;
                    atomicAdd(&sstat[c0], s[nt][0]);
                    atomicAdd(&sstat[c0 + 1], s[nt][1]);
                    atomicAdd(&sstat[256 + c0], q[nt][0]);
                    atomicAdd(&sstat[256 + c0 + 1], q[nt][1]);
                }
            }
        }
    };

    const int rem = ntiles - (int)blockIdx.x;
    const int nIter = rem > 0 ? (rem + grid - 1) / grid : 0;

    if (nIter > 0) {
        prefetch(blockIdx.x, 0, 0); CP_COMMIT();
        prefetch(blockIdx.x, 1, 1); CP_COMMIT();
        int buf = 0;
        for (int it = 0; it < nIter; it++) {
            const int tile = blockIdx.x + it * grid;
            const int tnext = tile + grid;
            CP_WAIT1(); __syncthreads();
            compute(buf, 0);
            __syncthreads();
            if (tnext < ntiles) prefetch(tnext, 0, buf);
            CP_COMMIT();
            buf ^= 1;
            CP_WAIT1(); __syncthreads();
            compute(buf, 1);
            __syncthreads();
            if (tnext < ntiles) prefetch(tnext, 1, buf);
            CP_COMMIT();
            buf ^= 1;
            epilogue(tile);
        }
    }
    __syncthreads();
    if (MODE == 1) {
        if (tid < 512) atomicAdd(&g_stats1[tid], sstat[tid]);
    }
}

// ---------------- BN1 finalize ----------------
__global__ void finalize1_kernel(const float* __restrict__ gamma1,
                                 const float* __restrict__ beta1, float invE) {
    const int j = threadIdx.x;
    const float mu  = g_stats1[j] * invE;
    const float var = g_stats1[FF + j] * invE - mu * mu;
    const float s   = gamma1[j] * rsqrtf(var + EPS);
    g_scale[j] = s;
    g_shift[j] = beta1[j] - mu * s;
}

// ---------------- gate + scatter (vector atomics) ----------------
__global__ void gate_scatter_kernel(const void* __restrict__ ibuf, int E) {
    __shared__ float ssc[FF], ssh[FF];
    ssc[threadIdx.x] = g_scale[threadIdx.x];
    ssh[threadIdx.x] = g_shift[threadIdx.x];
    __syncthreads();
    const int is64 = g_is64;
    const long long total  = (long long)E * 32;
    const long long stride = (long long)gridDim.x * blockDim.x;
    for (long long t = (long long)blockIdx.x * blockDim.x + threadIdx.x;
         t < total; t += stride) {
        const long long e = t >> 5;
        const int c4 = (int)(t & 31) << 2;
        const float4 f = *(const float4*)(g_h + e * FF + c4);
        const float4 g = *(const float4*)(g_h + e * FF + HN + c4);
        float4 m;
        m.x = sigmoidf_(f.x * ssc[c4 + 0] + ssh[c4 + 0]) * tanhf_(g.x * ssc[HN + c4 + 0] + ssh[HN + c4 + 0]);
        m.y = sigmoidf_(f.y * ssc[c4 + 1] + ssh[c4 + 1]) * tanhf_(g.y * ssc[HN + c4 + 1] + ssh[HN + c4 + 1]);
        m.z = sigmoidf_(f.z * ssc[c4 + 2] + ssh[c4 + 2]) * tanhf_(g.z * ssc[HN + c4 + 2] + ssh[HN + c4 + 2]);
        m.w = sigmoidf_(f.w * ssc[c4 + 3] + ssh[c4 + 3]) * tanhf_(g.w * ssc[HN + c4 + 3] + ssh[HN + c4 + 3]);
        const long long idx = is64 ? ((const long long*)ibuf)[e]
                                   : (long long)((const int*)ibuf)[e];
        float* dst = g_agg + idx * HN + c4;
        asm volatile("red.global.add.v4.f32 [%0], {%1, %2, %3, %4};"
                     :: "l"(dst), "f"(m.x), "f"(m.y), "f"(m.z), "f"(m.w) : "memory");
    }
}

// ---------------- BN2 + final ----------------
__global__ void stats2_kernel(int N) {
    const int t = blockIdx.x * blockDim.x + threadIdx.x;
    const int col = t & (HN - 1);
    const int r0 = t >> 7;
    const int rs = (gridDim.x * blockDim.x) >> 7;
    float s = 0.f, sq = 0.f;
    for (long long r = r0; r < N; r += rs) {
        const float v = g_agg[r * HN + col];
        s += v; sq = fmaf(v, v, sq);
    }
    atomicAdd(&g_stats2[col], s);
    atomicAdd(&g_stats2[HN + col], sq);
}

__global__ void final_kernel(const float* __restrict__ node_emb,
                             const float* __restrict__ gamma2,
                             const float* __restrict__ beta2,
                             float* __restrict__ out, int total, float invN) {
    const int t = blockIdx.x * blockDim.x + threadIdx.x;
    if (t >= total) return;
    const int col = t & (HN - 1);
    const float mu  = g_stats2[col] * invN;
    const float var = g_stats2[HN + col] * invN - mu * mu;
    const float c1  = (g_agg[t] - mu) * rsqrtf(var + EPS) * gamma2[col] + beta2[col];
    out[t] = tanhf_(node_emb[t] + c1);
}

// ---------------- launch ----------------
extern "C" void kernel_launch(void* const* d_in, const int* in_sizes, int n_in,
                              void* d_out, int out_size) {
    const float* node_emb = (const float*)d_in[0];
    const float* edge_emb = (const float*)d_in[1];
    const void*  ibuf     = d_in[2];
    const float* W1       = (const float*)d_in[3];
    const float* b1       = (const float*)d_in[4];
    const float* gamma1   = (const float*)d_in[5];
    const float* beta1    = (const float*)d_in[6];
    const float* gamma2   = (const float*)d_in[7];
    const float* beta2    = (const float*)d_in[8];
    float* out = (float*)d_out;

    const int N = in_sizes[0] / HN;
    const int E = in_sizes[1] / HN;

    static bool attr_done = false;
    if (!attr_done) {
        cudaFuncSetAttribute(mma_gemm<0>, cudaFuncAttributeMaxDynamicSharedMemorySize, SMEM_SZ);
        cudaFuncSetAttribute(mma_gemm<1>, cudaFuncAttributeMaxDynamicSharedMemorySize, SMEM_SZ);
        attr_done = true;
    }

    float* g_P_ptr; cudaGetSymbolAddress((void**)&g_P_ptr, g_P);
    float* g_h_ptr; cudaGetSymbolAddress((void**)&g_h_ptr, g_h);

    detect_kernel<<<1, 32>>>((const unsigned*)ibuf);
    zero_kernel<<<4096, 256>>>(N * HN);
    prepW_kernel<<<256, 256>>>(W1);

    mma_gemm<0><<<148, 512, SMEM_SZ>>>(node_emb, b1, ibuf, g_P_ptr, N);
    mma_gemm<1><<<148, 512, SMEM_SZ>>>(edge_emb, b1, ibuf, g_h_ptr, E);

    finalize1_kernel<<<1, 256>>>(gamma1, beta1, 1.0f / (float)E);
    gate_scatter_kernel<<<8192, 256>>>(ibuf, E);

    stats2_kernel<<<1024, 256>>>(N);
    final_kernel<<<(N * HN + 255) / 256, 256>>>(node_emb, gamma2, beta2, out,
                                                N * HN, 1.0f / (float)N);
}

// round 6
// speedup vs baseline: 2.6701x; 1.0924x over previous
#include <cuda_runtime.h>
#include <cuda_fp16.h>
#include <cstdint>

#define HN 128
#define FF 256
#define NMAX 50048
#define EMAX 800000
#define EPS 1e-5f

// ---------------- static scratch ----------------
__device__ float  g_P[(size_t)NMAX * FF];
__device__ __half g_h16[(size_t)EMAX * FF];   // pre-BN h, fp16
__device__ float  g_agg[(size_t)NMAX * HN];
__device__ float  g_Wt[2][32768];             // B prepacked in mma-frag order
__device__ float  g_stats1[2 * FF];
__device__ float  g_stats2[2 * HN];
__device__ float  g_scale[FF];
__device__ float  g_shift[FF];
__device__ int    g_is64;

// ---------------- helpers ----------------
__device__ __forceinline__ uint32_t smem_u32(const void* p) {
    uint32_t a;
    asm("{ .reg .u64 t; cvta.to.shared.u64 t, %1; cvt.u32.u64 %0, t; }" : "=r"(a) : "l"(p));
    return a;
}
__device__ __forceinline__ float tf32r(float x) {
    float y; asm("cvt.rna.tf32.f32 %0, %1;" : "=f"(y) : "f"(x)); return y;
}
__device__ __forceinline__ float sigmoidf_(float x) {
    return __fdividef(1.f, 1.f + __expf(-x));
}
__device__ __forceinline__ float tanhf_(float x) {
    float t = __expf(2.f * x);
    return 1.f - __fdividef(2.f, t + 1.f);
}
__device__ __forceinline__ void cpasync16(uint32_t dst, const void* src, bool pred) {
    int sz = pred ? 16 : 0;
    asm volatile("cp.async.cg.shared.global [%0], [%1], 16, %2;"
                 :: "r"(dst), "l"(src), "r"(sz) : "memory");
}
#define CP_COMMIT() asm volatile("cp.async.commit_group;" ::: "memory")
#define CP_WAIT1()  asm volatile("cp.async.wait_group 1;" ::: "memory")

__device__ __forceinline__ void mma8(float* c, const uint32_t* a, uint32_t b0, uint32_t b1) {
    asm volatile("mma.sync.aligned.m16n8k8.row.col.f32.tf32.tf32.f32 "
                 "{%0,%1,%2,%3}, {%4,%5,%6,%7}, {%8,%9}, {%0,%1,%2,%3};"
                 : "+f"(c[0]), "+f"(c[1]), "+f"(c[2]), "+f"(c[3])
                 : "r"(a[0]), "r"(a[1]), "r"(a[2]), "r"(a[3]), "r"(b0), "r"(b1));
}
__device__ __forceinline__ void ldsm4(uint32_t* a, uint32_t addr) {
    asm volatile("ldmatrix.sync.aligned.m8n8.x4.shared.b16 {%0,%1,%2,%3}, [%4];"
                 : "=r"(a[0]), "=r"(a[1]), "=r"(a[2]), "=r"(a[3]) : "r"(addr));
}

// SMEM map (bytes)
#define AS_STRIDE 68
#define BS_OFF    0
#define AS_OFF    131072               // B: 32768 floats frag-packed
#define AS_SZ     34816                // 128*68*4
#define SSTAT_OFF 200704
#define SMEM_SZ   202752

// ---------------- small kernels ----------------
__global__ void detect_kernel(const unsigned* __restrict__ u) {
    unsigned v = 0;
    for (int k = threadIdx.x; k < 64; k += 32) v |= u[2 * k + 1];
#pragma unroll
    for (int o = 16; o; o >>= 1) v |= __shfl_xor_sync(0xffffffffu, v, o);
    if (threadIdx.x == 0) g_is64 = (v == 0) ? 1 : 0;
}

__global__ void zero_kernel(int aggCount) {
    const int stride = gridDim.x * blockDim.x;
    const int t0 = blockIdx.x * blockDim.x + threadIdx.x;
    for (int j = t0; j < aggCount; j += stride) g_agg[j] = 0.f;
    if (t0 < 2 * FF) g_stats1[t0] = 0.f;
    if (t0 < 2 * HN) g_stats2[t0] = 0.f;
}

// B prepack (unchanged from R5)
__global__ void prepW_kernel(const float* __restrict__ W1) {
    const int gid = blockIdx.x * blockDim.x + threadIdx.x;
    if (gid >= 65536) return;
    const int mode = gid >> 15;
    const int u = gid & 32767;
    const int r = u & 3, lane = (u >> 2) & 31, nt = (u >> 7) & 3;
    const int kpw = u >> 9, wn = kpw >> 3, kpair = kpw & 7;
    const int ks = kpair * 2 + (r >> 1), j = r & 1;
    const int k = ks * 8 + (lane & 3) + j * 4;
    const int n = wn * 32 + nt * 8 + (lane >> 2);
    g_Wt[mode][u] = tf32r(W1[(k + mode * HN) * FF + n]);
}

// ---------------- warp-mma TF32 GEMM (16 warps, ldmatrix A) ----------------
// MODE 0: g_P (fp32) = node_emb @ W_top + b1
// MODE 1: g_h16 (fp16) = edge_emb @ W_bot + g_P[i[row]]  (+ fused BN1 stats)
template <int MODE>
__global__ void __launch_bounds__(512, 1) mma_gemm(
    const float* __restrict__ A, const float* __restrict__ b1,
    const void* __restrict__ ibuf, void* __restrict__ outv, int M)
{
    extern __shared__ char smem[];
    float* Bs  = (float*)(smem + BS_OFF);
    float* As0 = (float*)(smem + AS_OFF);
    float* As1 = (float*)(smem + AS_OFF + AS_SZ);
    float* sstat = (float*)(smem + SSTAT_OFF);
    const uint32_t as_u0 = smem_u32(As0);
    const uint32_t as_u1 = smem_u32(As1);

    const int tid = threadIdx.x, lane = tid & 31, wid = tid >> 5;
    const int wm = wid & 1, wn = wid >> 1;
    const int ntiles = (M + 127) >> 7;
    const int grid = gridDim.x;
    const int is64 = (MODE == 1) ? g_is64 : 0;

    // B (frag-packed) straight copy
    for (int i = tid * 4; i < 32768; i += 512 * 4)
        *(float4*)(Bs + i) = *(const float4*)(g_Wt[MODE] + i);
    if (MODE == 1) sstat[tid] = 0.f;
    __syncthreads();

    float acc[4][4][4];
#pragma unroll
    for (int mt = 0; mt < 4; mt++)
#pragma unroll
        for (int nt = 0; nt < 4; nt++)
#pragma unroll
            for (int r = 0; r < 4; r++) acc[mt][nt][r] = 0.f;

    // ldmatrix per-lane base offsets: matrix m = lane>>3
    //   m0: (row+ (lane&7), k+0)   m1: (row+8+(lane&7), k+0)
    //   m2: (row+ (lane&7), k+4)   m3: (row+8+(lane&7), k+4)
    const int lrow = (lane & 7) + ((lane & 8) ? 8 : 0);
    const int lkof = (lane & 16) ? 4 : 0;
    uint32_t aoff[4];
#pragma unroll
    for (int mt = 0; mt < 4; mt++)
        aoff[mt] = (uint32_t)(((wm * 64 + mt * 16 + lrow) * AS_STRIDE + lkof) * 4);

    auto prefetch = [&](int tile, int kc, int b) {
        const long long rbase = (long long)tile << 7;
        const uint32_t au = b ? as_u1 : as_u0;
#pragma unroll
        for (int s = 0; s < 4; s++) {
            const int j = tid + s * 512;
            const int r = j >> 4, kq = (j & 15) << 2;
            const uint32_t dst = au + (uint32_t)(r * AS_STRIDE + kq) * 4u;
            const float* src = A + (rbase + r) * HN + kc * 64 + kq;
            cpasync16(dst, src, rbase + r < (long long)M);
        }
    };

    auto compute = [&](int b, int kc) {
        const uint32_t au = b ? as_u1 : as_u0;
        const float* bbase = Bs + (wn * 8 + kc * 4) * 512;
#pragma unroll
        for (int kp = 0; kp < 4; kp++) {
            float4 bp[4];
#pragma unroll
            for (int nt = 0; nt < 4; nt++)
                bp[nt] = *(const float4*)(bbase + (kp * 4 + nt) * 128 + lane * 4);
#pragma unroll
            for (int sub = 0; sub < 2; sub++) {
                const uint32_t kbyte = (uint32_t)((kp * 2 + sub) * 8 * 4);
                uint32_t a[4][4];
#pragma unroll
                for (int mt = 0; mt < 4; mt++)
                    ldsm4(a[mt], au + aoff[mt] + kbyte);
#pragma unroll
                for (int mt = 0; mt < 4; mt++)
#pragma unroll
                    for (int nt = 0; nt < 4; nt++) {
                        const uint32_t b0 = sub ? __float_as_uint(bp[nt].z) : __float_as_uint(bp[nt].x);
                        const uint32_t b1r = sub ? __float_as_uint(bp[nt].w) : __float_as_uint(bp[nt].y);
                        mma8(acc[mt][nt], a[mt], b0, b1r);
                    }
            }
        }
    };

    auto epilogue = [&](int tile) {
        const long long rbase = (long long)tile << 7;
        float s[4][2], q[4][2];
        if (MODE == 1) {
#pragma unroll
            for (int nt = 0; nt < 4; nt++) {
                s[nt][0] = s[nt][1] = 0.f; q[nt][0] = q[nt][1] = 0.f;
            }
        }
#pragma unroll
        for (int mt = 0; mt < 4; mt++) {
            long long pb[2]; bool valid[2]; long long rown[2];
#pragma unroll
            for (int h = 0; h < 2; h++) {
                const long long row = rbase + wm * 64 + mt * 16 + (lane >> 2) + h * 8;
                rown[h] = row;
                valid[h] = row < (long long)M;
                pb[h] = 0;
                if (MODE == 1 && valid[h]) {
                    const long long idx = is64 ? ((const long long*)ibuf)[row]
                                               : (long long)((const int*)ibuf)[row];
                    pb[h] = idx * FF;
                }
            }
#pragma unroll
            for (int nt = 0; nt < 4; nt++) {
                const int c0 = wn * 32 + nt * 8 + 2 * (lane & 3);
#pragma unroll
                for (int h = 0; h < 2; h++) {
                    if (!valid[h]) continue;
                    float2 add;
                    if (MODE == 0) add = *(const float2*)(b1 + c0);
                    else           add = *(const float2*)(g_P + pb[h] + c0);
                    float2 o;
                    o.x = acc[mt][nt][2 * h] + add.x;
                    o.y = acc[mt][nt][2 * h + 1] + add.y;
                    if (MODE == 0) {
                        *(float2*)((float*)outv + rown[h] * FF + c0) = o;
                    } else {
                        *(__half2*)((__half*)outv + rown[h] * FF + c0) =
                            __floats2half2_rn(o.x, o.y);
                        s[nt][0] += o.x; q[nt][0] = fmaf(o.x, o.x, q[nt][0]);
                        s[nt][1] += o.y; q[nt][1] = fmaf(o.y, o.y, q[nt][1]);
                    }
                }
                acc[mt][nt][0] = 0.f; acc[mt][nt][1] = 0.f;
                acc[mt][nt][2] = 0.f; acc[mt][nt][3] = 0.f;
            }
        }
        if (MODE == 1) {
#pragma unroll
            for (int o = 4; o < 32; o <<= 1) {
#pragma unroll
                for (int nt = 0; nt < 4; nt++) {
                    s[nt][0] += __shfl_xor_sync(0xffffffffu, s[nt][0], o);
                    s[nt][1] += __shfl_xor_sync(0xffffffffu, s[nt][1], o);
                    q[nt][0] += __shfl_xor_sync(0xffffffffu, q[nt][0], o);
                    q[nt][1] += __shfl_xor_sync(0xffffffffu, q[nt][1], o);
                }
            }
            if (lane < 4) {
#pragma unroll
                for (int nt = 0; nt < 4; nt++) {
                    const int c0 = wn * 32 + nt * 8 + 2 * lane;
                    atomicAdd(&sstat[c0], s[nt][0]);
                    atomicAdd(&sstat[c0 + 1], s[nt][1]);
                    atomicAdd(&sstat[256 + c0], q[nt][0]);
                    atomicAdd(&sstat[256 + c0 + 1], q[nt][1]);
                }
            }
        }
    };

    const int rem = ntiles - (int)blockIdx.x;
    const int nIter = rem > 0 ? (rem + grid - 1) / grid : 0;

    if (nIter > 0) {
        prefetch(blockIdx.x, 0, 0); CP_COMMIT();
        prefetch(blockIdx.x, 1, 1); CP_COMMIT();
        int buf = 0;
        for (int it = 0; it < nIter; it++) {
            const int tile = blockIdx.x + it * grid;
            const int tnext = tile + grid;
            CP_WAIT1(); __syncthreads();
            compute(buf, 0);
            __syncthreads();
            if (tnext < ntiles) prefetch(tnext, 0, buf);
            CP_COMMIT();
            buf ^= 1;
            CP_WAIT1(); __syncthreads();
            compute(buf, 1);
            __syncthreads();
            if (tnext < ntiles) prefetch(tnext, 1, buf);
            CP_COMMIT();
            buf ^= 1;
            epilogue(tile);
        }
    }
    __syncthreads();
    if (MODE == 1) {
        atomicAdd(&g_stats1[tid], sstat[tid]);
    }
}

// ---------------- BN1 finalize ----------------
__global__ void finalize1_kernel(const float* __restrict__ gamma1,
                                 const float* __restrict__ beta1, float invE) {
    const int j = threadIdx.x;
    const float mu  = g_stats1[j] * invE;
    const float var = g_stats1[FF + j] * invE - mu * mu;
    const float s   = gamma1[j] * rsqrtf(var + EPS);
    g_scale[j] = s;
    g_shift[j] = beta1[j] - mu * s;
}

// ---------------- gate + scatter (fp16 h, vector atomics) ----------------
__global__ void gate_scatter_kernel(const void* __restrict__ ibuf, int E) {
    __shared__ float ssc[FF], ssh[FF];
    ssc[threadIdx.x] = g_scale[threadIdx.x];
    ssh[threadIdx.x] = g_shift[threadIdx.x];
    __syncthreads();
    const int is64 = g_is64;
    const long long total  = (long long)E * 32;
    const long long stride = (long long)gridDim.x * blockDim.x;
    for (long long t = (long long)blockIdx.x * blockDim.x + threadIdx.x;
         t < total; t += stride) {
        const long long e = t >> 5;
        const int c4 = (int)(t & 31) << 2;
        const __half* hrow = g_h16 + e * FF;
        const __half2 f01 = *(const __half2*)(hrow + c4);
        const __half2 f23 = *(const __half2*)(hrow + c4 + 2);
        const __half2 g01 = *(const __half2*)(hrow + HN + c4);
        const __half2 g23 = *(const __half2*)(hrow + HN + c4 + 2);
        const float2 fa = __half22float2(f01), fb = __half22float2(f23);
        const float2 ga = __half22float2(g01), gb = __half22float2(g23);
        float4 m;
        m.x = sigmoidf_(fa.x * ssc[c4 + 0] + ssh[c4 + 0]) * tanhf_(ga.x * ssc[HN + c4 + 0] + ssh[HN + c4 + 0]);
        m.y = sigmoidf_(fa.y * ssc[c4 + 1] + ssh[c4 + 1]) * tanhf_(ga.y * ssc[HN + c4 + 1] + ssh[HN + c4 + 1]);
        m.z = sigmoidf_(fb.x * ssc[c4 + 2] + ssh[c4 + 2]) * tanhf_(gb.x * ssc[HN + c4 + 2] + ssh[HN + c4 + 2]);
        m.w = sigmoidf_(fb.y * ssc[c4 + 3] + ssh[c4 + 3]) * tanhf_(gb.y * ssc[HN + c4 + 3] + ssh[HN + c4 + 3]);
        const long long idx = is64 ? ((const long long*)ibuf)[e]
                                   : (long long)((const int*)ibuf)[e];
        float* dst = g_agg + idx * HN + c4;
        asm volatile("red.global.add.v4.f32 [%0], {%1, %2, %3, %4};"
                     :: "l"(dst), "f"(m.x), "f"(m.y), "f"(m.z), "f"(m.w) : "memory");
    }
}

// ---------------- BN2 + final ----------------
__global__ void stats2_kernel(int N) {
    const int t = blockIdx.x * blockDim.x + threadIdx.x;
    const int col = t & (HN - 1);
    const int r0 = t >> 7;
    const int rs = (gridDim.x * blockDim.x) >> 7;
    float s = 0.f, sq = 0.f;
    for (long long r = r0; r < N; r += rs) {
        const float v = g_agg[r * HN + col];
        s += v; sq = fmaf(v, v, sq);
    }
    atomicAdd(&g_stats2[col], s);
    atomicAdd(&g_stats2[HN + col], sq);
}

__global__ void final_kernel(const float* __restrict__ node_emb,
                             const float* __restrict__ gamma2,
                             const float* __restrict__ beta2,
                             float* __restrict__ out, int total, float invN) {
    const int t = blockIdx.x * blockDim.x + threadIdx.x;
    if (t >= total) return;
    const int col = t & (HN - 1);
    const float mu  = g_stats2[col] * invN;
    const float var = g_stats2[HN + col] * invN - mu * mu;
    const float c1  = (g_agg[t] - mu) * rsqrtf(var + EPS) * gamma2[col] + beta2[col];
    out[t] = tanhf_(node_emb[t] + c1);
}

// ---------------- launch ----------------
extern "C" void kernel_launch(void* const* d_in, const int* in_sizes, int n_in,
                              void* d_out, int out_size) {
    const float* node_emb = (const float*)d_in[0];
    const float* edge_emb = (const float*)d_in[1];
    const void*  ibuf     = d_in[2];
    const float* W1       = (const float*)d_in[3];
    const float* b1       = (const float*)d_in[4];
    const float* gamma1   = (const float*)d_in[5];
    const float* beta1    = (const float*)d_in[6];
    const float* gamma2   = (const float*)d_in[7];
    const float* beta2    = (const float*)d_in[8];
    float* out = (float*)d_out;

    const int N = in_sizes[0] / HN;
    const int E = in_sizes[1] / HN;

    static bool attr_done = false;
    if (!attr_done) {
        cudaFuncSetAttribute(mma_gemm<0>, cudaFuncAttributeMaxDynamicSharedMemorySize, SMEM_SZ);
        cudaFuncSetAttribute(mma_gemm<1>, cudaFuncAttributeMaxDynamicSharedMemorySize, SMEM_SZ);
        attr_done = true;
    }

    float* g_P_ptr;  cudaGetSymbolAddress((void**)&g_P_ptr, g_P);
    __half* g_h_ptr; cudaGetSymbolAddress((void**)&g_h_ptr, g_h16);

    detect_kernel<<<1, 32>>>((const unsigned*)ibuf);
    zero_kernel<<<4096, 256>>>(N * HN);
    prepW_kernel<<<256, 256>>>(W1);

    mma_gemm<0><<<148, 512, SMEM_SZ>>>(node_emb, b1, ibuf, g_P_ptr, N);
    mma_gemm<1><<<148, 512, SMEM_SZ>>>(edge_emb, b1, ibuf, g_h_ptr, E);

    finalize1_kernel<<<1, 256>>>(gamma1, beta1, 1.0f / (float)E);
    gate_scatter_kernel<<<8192, 256>>>(ibuf, E);

    stats2_kernel<<<1024, 256>>>(N);
    final_kernel<<<(N * HN + 255) / 256, 256>>>(node_emb, gamma2, beta2, out,
                                                N * HN, 1.0f / (float)N);
}

// round 7
// speedup vs baseline: 2.8683x; 1.0743x over previous
#include <cuda_runtime.h>
#include <cuda_fp16.h>
#include <cstdint>

#define HN 128
#define FF 256
#define NMAX 50048
#define EMAX 800000
#define EPS 1e-5f

// ---------------- static scratch ----------------
__device__ float  g_P[(size_t)NMAX * FF];
__device__ __half g_h16[(size_t)EMAX * FF];     // pre-BN h, fp16
__device__ float  g_agg[(size_t)NMAX * HN];
__device__ float  g_Wt[2][2][16384];            // [mode][half] frag-packed B
__device__ float  g_stats1[2 * FF];
__device__ float  g_stats2[2 * HN];
__device__ float  g_scale[FF];
__device__ float  g_shift[FF];
__device__ int    g_is64;

// ---------------- helpers ----------------
__device__ __forceinline__ uint32_t smem_u32(const void* p) {
    uint32_t a;
    asm("{ .reg .u64 t; cvta.to.shared.u64 t, %1; cvt.u32.u64 %0, t; }" : "=r"(a) : "l"(p));
    return a;
}
__device__ __forceinline__ float tf32r(float x) {
    float y; asm("cvt.rna.tf32.f32 %0, %1;" : "=f"(y) : "f"(x)); return y;
}
__device__ __forceinline__ float sigmoidf_(float x) {
    return __fdividef(1.f, 1.f + __expf(-x));
}
__device__ __forceinline__ float tanhf_(float x) {
    float t = __expf(2.f * x);
    return 1.f - __fdividef(2.f, t + 1.f);
}
__device__ __forceinline__ void cpasync16(uint32_t dst, const void* src, bool pred) {
    int sz = pred ? 16 : 0;
    asm volatile("cp.async.cg.shared.global [%0], [%1], 16, %2;"
                 :: "r"(dst), "l"(src), "r"(sz) : "memory");
}
#define CP_COMMIT() asm volatile("cp.async.commit_group;" ::: "memory")
#define CP_WAIT1()  asm volatile("cp.async.wait_group 1;" ::: "memory")

__device__ __forceinline__ void mma8(float* c, const uint32_t* a, uint32_t b0, uint32_t b1) {
    asm volatile("mma.sync.aligned.m16n8k8.row.col.f32.tf32.tf32.f32 "
                 "{%0,%1,%2,%3}, {%4,%5,%6,%7}, {%8,%9}, {%0,%1,%2,%3};"
                 : "+f"(c[0]), "+f"(c[1]), "+f"(c[2]), "+f"(c[3])
                 : "r"(a[0]), "r"(a[1]), "r"(a[2]), "r"(a[3]), "r"(b0), "r"(b1));
}
__device__ __forceinline__ void ldsm4(uint32_t* a, uint32_t addr) {
    asm volatile("ldmatrix.sync.aligned.m8n8.x4.shared.b16 {%0,%1,%2,%3}, [%4];"
                 : "=r"(a[0]), "=r"(a[1]), "=r"(a[2]), "=r"(a[3]) : "r"(addr));
}

// SMEM map (bytes): Bs 64KB | As0 18KB | As1 18KB | sstat 1KB  => 103424 (2 CTAs/SM)
#define AS_STRIDE 36
#define AS_OFF    65536
#define AS_BYTES  18432                 // 128*36*4
#define SSTAT_OFF (AS_OFF + 2 * AS_BYTES)
#define SMEM_SZ   (SSTAT_OFF + 1024)

// ---------------- small kernels ----------------
__global__ void detect_kernel(const unsigned* __restrict__ u) {
    unsigned v = 0;
    for (int k = threadIdx.x; k < 64; k += 32) v |= u[2 * k + 1];
#pragma unroll
    for (int o = 16; o; o >>= 1) v |= __shfl_xor_sync(0xffffffffu, v, o);
    if (threadIdx.x == 0) g_is64 = (v == 0) ? 1 : 0;
}

__global__ void zero_kernel(int aggCount) {
    const int stride = gridDim.x * blockDim.x;
    const int t0 = blockIdx.x * blockDim.x + threadIdx.x;
    for (int j = t0; j < aggCount; j += stride) g_agg[j] = 0.f;
    if (t0 < 2 * FF) g_stats1[t0] = 0.f;
    if (t0 < 2 * HN) g_stats2[t0] = 0.f;
}

// B prepack per (mode, half): u = ((wn*8 + kpair)*4 + nt)*128 + lane*4 + r
__global__ void prepW_kernel(const float* __restrict__ W1) {
    const int gid = blockIdx.x * blockDim.x + threadIdx.x;
    if (gid >= 65536) return;
    const int mode = gid >> 15;
    const int half = (gid >> 14) & 1;
    const int u = gid & 16383;
    const int r = u & 3, lane = (u >> 2) & 31, nt = (u >> 7) & 3;
    const int kpw = u >> 9;                 // 0..31
    const int wn = kpw >> 3, kpair = kpw & 7;
    const int ks = kpair * 2 + (r >> 1), j = r & 1;
    const int k = ks * 8 + (lane & 3) + j * 4;
    const int n = half * 128 + wn * 32 + nt * 8 + (lane >> 2);
    g_Wt[mode][half][u] = tf32r(W1[(k + mode * HN) * FF + n]);
}

// ---------------- warp-mma TF32 GEMM: 256 thr, 2 CTAs/SM, N-split halves ----
// Job j: tile = j>>1, half = j&1. Grid even => half constant per CTA.
// Warp (wm=wid&1, wn=wid>>1) owns rows wm*64+[0,64), local cols wn*32+[0,32).
template <int MODE>
__global__ void __launch_bounds__(256, 2) mma_gemm(
    const float* __restrict__ A, const float* __restrict__ b1,
    const void* __restrict__ ibuf, void* __restrict__ outv, int M)
{
    extern __shared__ char smem[];
    float* Bs  = (float*)smem;
    float* sstat = (float*)(smem + SSTAT_OFF);
    const uint32_t as_u0 = smem_u32(smem + AS_OFF);
    const uint32_t as_u1 = smem_u32(smem + AS_OFF + AS_BYTES);

    const int tid = threadIdx.x, lane = tid & 31, wid = tid >> 5;
    const int wm = wid & 1, wn = wid >> 1;
    const int ntiles = (M + 127) >> 7;
    const long long njobs = (long long)ntiles * 2;
    const int G = gridDim.x;
    const int half = blockIdx.x & 1;
    const int is64 = (MODE == 1) ? g_is64 : 0;

    // B pack copy (16384 floats)
    for (int i = tid * 4; i < 16384; i += 256 * 4)
        *(float4*)(Bs + i) = *(const float4*)(g_Wt[MODE][half] + i);
    if (MODE == 1) { sstat[tid] = 0.f; }
    __syncthreads();

    float acc[4][4][4];
#pragma unroll
    for (int mt = 0; mt < 4; mt++)
#pragma unroll
        for (int nt = 0; nt < 4; nt++)
#pragma unroll
            for (int r = 0; r < 4; r++) acc[mt][nt][r] = 0.f;

    const int lrow = (lane & 7) + ((lane & 8) ? 8 : 0);
    const int lkof = (lane & 16) ? 4 : 0;
    uint32_t aoff[4];
#pragma unroll
    for (int mt = 0; mt < 4; mt++)
        aoff[mt] = (uint32_t)(((wm * 64 + mt * 16 + lrow) * AS_STRIDE + lkof) * 4);

    // prefetch one 128x32 A chunk
    auto prefetchChunk = [&](long long pjob, int kc, int b) {
        const long long tile = pjob >> 1;
        const long long rbase = tile << 7;
        const uint32_t au = b ? as_u1 : as_u0;
        const bool jobok = pjob < njobs;
#pragma unroll
        for (int s = 0; s < 4; s++) {
            const int j2 = tid + s * 256;       // 0..1023
            const int r = j2 >> 3, kq = (j2 & 7) << 2;
            const uint32_t dst = au + (uint32_t)(r * AS_STRIDE + kq) * 4u;
            const float* src = A + (rbase + r) * HN + kc * 32 + kq;
            cpasync16(dst, src, jobok && (rbase + r < (long long)M));
        }
    };

    auto compute = [&](int b, int kc) {
        const uint32_t au = b ? as_u1 : as_u0;
        const float* bbase = Bs + (wn * 8 + kc * 2) * 512;
#pragma unroll
        for (int kp = 0; kp < 2; kp++) {
            float4 bp[4];
#pragma unroll
            for (int nt = 0; nt < 4; nt++)
                bp[nt] = *(const float4*)(bbase + kp * 512 + nt * 128 + lane * 4);
#pragma unroll
            for (int sub = 0; sub < 2; sub++) {
                const uint32_t kbyte = (uint32_t)((kp * 2 + sub) * 8 * 4);
                uint32_t a[4][4];
#pragma unroll
                for (int mt = 0; mt < 4; mt++)
                    ldsm4(a[mt], au + aoff[mt] + kbyte);
#pragma unroll
                for (int mt = 0; mt < 4; mt++)
#pragma unroll
                    for (int nt = 0; nt < 4; nt++) {
                        const uint32_t b0 = sub ? __float_as_uint(bp[nt].z) : __float_as_uint(bp[nt].x);
                        const uint32_t b1r = sub ? __float_as_uint(bp[nt].w) : __float_as_uint(bp[nt].y);
                        mma8(acc[mt][nt], a[mt], b0, b1r);
                    }
            }
        }
    };

    auto epilogue = [&](long long tile) {
        const long long rbase = tile << 7;
        float s[4][2], q[4][2];
        if (MODE == 1) {
#pragma unroll
            for (int nt = 0; nt < 4; nt++) {
                s[nt][0] = s[nt][1] = 0.f; q[nt][0] = q[nt][1] = 0.f;
            }
        }
#pragma unroll
        for (int mt = 0; mt < 4; mt++) {
            long long pb[2]; bool valid[2]; long long rown[2];
#pragma unroll
            for (int h = 0; h < 2; h++) {
                const long long row = rbase + wm * 64 + mt * 16 + (lane >> 2) + h * 8;
                rown[h] = row;
                valid[h] = row < (long long)M;
                pb[h] = 0;
                if (MODE == 1 && valid[h]) {
                    const long long idx = is64 ? ((const long long*)ibuf)[row]
                                               : (long long)((const int*)ibuf)[row];
                    pb[h] = idx * FF;
                }
            }
#pragma unroll
            for (int nt = 0; nt < 4; nt++) {
                const int c0 = half * 128 + wn * 32 + nt * 8 + 2 * (lane & 3);
#pragma unroll
                for (int h = 0; h < 2; h++) {
                    if (!valid[h]) continue;
                    float2 add;
                    if (MODE == 0) add = *(const float2*)(b1 + c0);
                    else           add = *(const float2*)(g_P + pb[h] + c0);
                    float2 o;
                    o.x = acc[mt][nt][2 * h] + add.x;
                    o.y = acc[mt][nt][2 * h + 1] + add.y;
                    if (MODE == 0) {
                        *(float2*)((float*)outv + rown[h] * FF + c0) = o;
                    } else {
                        *(__half2*)((__half*)outv + rown[h] * FF + c0) =
                            __floats2half2_rn(o.x, o.y);
                        s[nt][0] += o.x; q[nt][0] = fmaf(o.x, o.x, q[nt][0]);
                        s[nt][1] += o.y; q[nt][1] = fmaf(o.y, o.y, q[nt][1]);
                    }
                }
                acc[mt][nt][0] = 0.f; acc[mt][nt][1] = 0.f;
                acc[mt][nt][2] = 0.f; acc[mt][nt][3] = 0.f;
            }
        }
        if (MODE == 1) {
#pragma unroll
            for (int o = 4; o < 32; o <<= 1) {
#pragma unroll
                for (int nt = 0; nt < 4; nt++) {
                    s[nt][0] += __shfl_xor_sync(0xffffffffu, s[nt][0], o);
                    s[nt][1] += __shfl_xor_sync(0xffffffffu, s[nt][1], o);
                    q[nt][0] += __shfl_xor_sync(0xffffffffu, q[nt][0], o);
                    q[nt][1] += __shfl_xor_sync(0xffffffffu, q[nt][1], o);
                }
            }
            if (lane < 4) {
#pragma unroll
                for (int nt = 0; nt < 4; nt++) {
                    const int lc = wn * 32 + nt * 8 + 2 * lane;
                    atomicAdd(&sstat[lc], s[nt][0]);
                    atomicAdd(&sstat[lc + 1], s[nt][1]);
                    atomicAdd(&sstat[128 + lc], q[nt][0]);
                    atomicAdd(&sstat[128 + lc + 1], q[nt][1]);
                }
            }
        }
    };

    long long job = blockIdx.x;
    if (job < njobs) {
        long long pjob = job; int pk = 0;
        auto advance = [&] { if (++pk == 4) { pk = 0; pjob += G; } };
        prefetchChunk(pjob, pk, 0); CP_COMMIT(); advance();
        prefetchChunk(pjob, pk, 1); CP_COMMIT(); advance();
        int buf = 0;
        for (; job < njobs; job += G) {
            const long long tile = job >> 1;
#pragma unroll 1
            for (int kc = 0; kc < 4; kc++) {
                CP_WAIT1(); __syncthreads();
                compute(buf, kc);
                __syncthreads();
                prefetchChunk(pjob, pk, buf);
                CP_COMMIT(); advance();
                buf ^= 1;
            }
            epilogue(tile);
        }
    }
    if (MODE == 1) {
        __syncthreads();
        if (tid < 128) {
            atomicAdd(&g_stats1[half * 128 + tid], sstat[tid]);
            atomicAdd(&g_stats1[256 + half * 128 + tid], sstat[128 + tid]);
        }
    }
}

// ---------------- BN1 finalize ----------------
__global__ void finalize1_kernel(const float* __restrict__ gamma1,
                                 const float* __restrict__ beta1, float invE) {
    const int j = threadIdx.x;
    const float mu  = g_stats1[j] * invE;
    const float var = g_stats1[FF + j] * invE - mu * mu;
    const float s   = gamma1[j] * rsqrtf(var + EPS);
    g_scale[j] = s;
    g_shift[j] = beta1[j] - mu * s;
}

// ---------------- gate + scatter (fp16 h, vector atomics) ----------------
__global__ void gate_scatter_kernel(const void* __restrict__ ibuf, int E) {
    __shared__ float ssc[FF], ssh[FF];
    ssc[threadIdx.x] = g_scale[threadIdx.x];
    ssh[threadIdx.x] = g_shift[threadIdx.x];
    __syncthreads();
    const int is64 = g_is64;
    const long long total  = (long long)E * 32;
    const long long stride = (long long)gridDim.x * blockDim.x;
    for (long long t = (long long)blockIdx.x * blockDim.x + threadIdx.x;
         t < total; t += stride) {
        const long long e = t >> 5;
        const int c4 = (int)(t & 31) << 2;
        const __half* hrow = g_h16 + e * FF;
        const __half2 f01 = *(const __half2*)(hrow + c4);
        const __half2 f23 = *(const __half2*)(hrow + c4 + 2);
        const __half2 g01 = *(const __half2*)(hrow + HN + c4);
        const __half2 g23 = *(const __half2*)(hrow + HN + c4 + 2);
        const float2 fa = __half22float2(f01), fb = __half22float2(f23);
        const float2 ga = __half22float2(g01), gb = __half22float2(g23);
        float4 m;
        m.x = sigmoidf_(fa.x * ssc[c4 + 0] + ssh[c4 + 0]) * tanhf_(ga.x * ssc[HN + c4 + 0] + ssh[HN + c4 + 0]);
        m.y = sigmoidf_(fa.y * ssc[c4 + 1] + ssh[c4 + 1]) * tanhf_(ga.y * ssc[HN + c4 + 1] + ssh[HN + c4 + 1]);
        m.z = sigmoidf_(fb.x * ssc[c4 + 2] + ssh[c4 + 2]) * tanhf_(gb.x * ssc[HN + c4 + 2] + ssh[HN + c4 + 2]);
        m.w = sigmoidf_(fb.y * ssc[c4 + 3] + ssh[c4 + 3]) * tanhf_(gb.y * ssc[HN + c4 + 3] + ssh[HN + c4 + 3]);
        const long long idx = is64 ? ((const long long*)ibuf)[e]
                                   : (long long)((const int*)ibuf)[e];
        float* dst = g_agg + idx * HN + c4;
        asm volatile("red.global.add.v4.f32 [%0], {%1, %2, %3, %4};"
                     :: "l"(dst), "f"(m.x), "f"(m.y), "f"(m.z), "f"(m.w) : "memory");
    }
}

// ---------------- BN2 + final ----------------
__global__ void stats2_kernel(int N) {
    const int t = blockIdx.x * blockDim.x + threadIdx.x;
    const int col = t & (HN - 1);
    const int r0 = t >> 7;
    const int rs = (gridDim.x * blockDim.x) >> 7;
    float s = 0.f, sq = 0.f;
    for (long long r = r0; r < N; r += rs) {
        const float v = g_agg[r * HN + col];
        s += v; sq = fmaf(v, v, sq);
    }
    atomicAdd(&g_stats2[col], s);
    atomicAdd(&g_stats2[HN + col], sq);
}

__global__ void final_kernel(const float* __restrict__ node_emb,
                             const float* __restrict__ gamma2,
                             const float* __restrict__ beta2,
                             float* __restrict__ out, int total, float invN) {
    const int t = blockIdx.x * blockDim.x + threadIdx.x;
    if (t >= total) return;
    const int col = t & (HN - 1);
    const float mu  = g_stats2[col] * invN;
    const float var = g_stats2[HN + col] * invN - mu * mu;
    const float c1  = (g_agg[t] - mu) * rsqrtf(var + EPS) * gamma2[col] + beta2[col];
    out[t] = tanhf_(node_emb[t] + c1);
}

// ---------------- launch ----------------
extern "C" void kernel_launch(void* const* d_in, const int* in_sizes, int n_in,
                              void* d_out, int out_size) {
    const float* node_emb = (const float*)d_in[0];
    const float* edge_emb = (const float*)d_in[1];
    const void*  ibuf     = d_in[2];
    const float* W1       = (const float*)d_in[3];
    const float* b1       = (const float*)d_in[4];
    const float* gamma1   = (const float*)d_in[5];
    const float* beta1    = (const float*)d_in[6];
    const float* gamma2   = (const float*)d_in[7];
    const float* beta2    = (const float*)d_in[8];
    float* out = (float*)d_out;

    const int N = in_sizes[0] / HN;
    const int E = in_sizes[1] / HN;

    static bool attr_done = false;
    if (!attr_done) {
        cudaFuncSetAttribute(mma_gemm<0>, cudaFuncAttributeMaxDynamicSharedMemorySize, SMEM_SZ);
        cudaFuncSetAttribute(mma_gemm<1>, cudaFuncAttributeMaxDynamicSharedMemorySize, SMEM_SZ);
        attr_done = true;
    }

    float* g_P_ptr;  cudaGetSymbolAddress((void**)&g_P_ptr, g_P);
    __half* g_h_ptr; cudaGetSymbolAddress((void**)&g_h_ptr, g_h16);

    detect_kernel<<<1, 32>>>((const unsigned*)ibuf);
    zero_kernel<<<4096, 256>>>(N * HN);
    prepW_kernel<<<256, 256>>>(W1);

    mma_gemm<0><<<296, 256, SMEM_SZ>>>(node_emb, b1, ibuf, g_P_ptr, N);
    mma_gemm<1><<<296, 256, SMEM_SZ>>>(edge_emb, b1, ibuf, g_h_ptr, E);

    finalize1_kernel<<<1, 256>>>(gamma1, beta1, 1.0f / (float)E);
    gate_scatter_kernel<<<8192, 256>>>(ibuf, E);

    stats2_kernel<<<1024, 256>>>(N);
    final_kernel<<<(N * HN + 255) / 256, 256>>>(node_emb, gamma2, beta2, out,
                                                N * HN, 1.0f / (float)N);
}

// round 8
// speedup vs baseline: 2.9180x; 1.0173x over previous
#include <cuda_runtime.h>
#include <cuda_fp16.h>
#include <cstdint>

#define HN 128
#define FF 256
#define NMAX 50048
#define EMAX 800000
#define EPS 1e-5f
#define NBLK_N (NMAX / 64)    // 782
#define NBLK_E (EMAX / 64)    // 12500

// ---------------- static scratch ----------------
__device__ float  g_P[(size_t)NMAX * FF];
__device__ __half g_h16[(size_t)EMAX * FF];
__device__ float  g_agg[(size_t)NMAX * HN];
__device__ uint4  g_Ae[(size_t)NBLK_E * 1024];   // edge A, fp16 frag-packed
__device__ uint4  g_An[(size_t)NBLK_N * 1024];   // node A, fp16 frag-packed
__device__ uint2  g_Wt16[2][2][4096];            // [mode][half] B fp16 frag-packed
__device__ float  g_stats1[2 * FF];
__device__ float  g_stats2[2 * HN];
__device__ float  g_scale[FF];
__device__ float  g_shift[FF];
__device__ int    g_is64;

// ---------------- helpers ----------------
__device__ __forceinline__ float sigmoidf_(float x) {
    return __fdividef(1.f, 1.f + __expf(-x));
}
__device__ __forceinline__ float tanhf_(float x) {
    float t = __expf(2.f * x);
    return 1.f - __fdividef(2.f, t + 1.f);
}
__device__ __forceinline__ void mma16(float* c, const uint4 a, const uint2 b) {
    asm volatile("mma.sync.aligned.m16n8k16.row.col.f32.f16.f16.f32 "
                 "{%0,%1,%2,%3},{%4,%5,%6,%7},{%8,%9},{%0,%1,%2,%3};"
                 : "+f"(c[0]), "+f"(c[1]), "+f"(c[2]), "+f"(c[3])
                 : "r"(a.x), "r"(a.y), "r"(a.z), "r"(a.w), "r"(b.x), "r"(b.y));
}
__device__ __forceinline__ uint32_t h2u(__half2 h) {
    return *reinterpret_cast<uint32_t*>(&h);
}

// ---------------- small kernels ----------------
__global__ void detect_kernel(const unsigned* __restrict__ u) {
    unsigned v = 0;
    for (int k = threadIdx.x; k < 64; k += 32) v |= u[2 * k + 1];
#pragma unroll
    for (int o = 16; o; o >>= 1) v |= __shfl_xor_sync(0xffffffffu, v, o);
    if (threadIdx.x == 0) g_is64 = (v == 0) ? 1 : 0;
}

__global__ void zero_kernel(int aggCount) {
    const int stride = gridDim.x * blockDim.x;
    const int t0 = blockIdx.x * blockDim.x + threadIdx.x;
    for (int j = t0; j < aggCount; j += stride) g_agg[j] = 0.f;
    if (t0 < 2 * FF) g_stats1[t0] = 0.f;
    if (t0 < 2 * HN) g_stats2[t0] = 0.f;
}

// A pack: unit gid = ((block*8 + ks)*4 + mt)*32 + lane -> one uint4 (a0..a3)
// a0={A[r0][c0],A[r0][c0+1]} a1={A[r1][...]}, a2/a3 at c0+8; r0=block*64+mt*16+(lane>>2)
__global__ void prepA_kernel(const float* __restrict__ A, uint4* __restrict__ dst,
                             int M, int nunits) {
    const int gid = blockIdx.x * blockDim.x + threadIdx.x;
    if (gid >= nunits) return;
    const int lane = gid & 31, mt = (gid >> 5) & 3, ks = (gid >> 7) & 7;
    const int block = gid >> 10;
    const int r0 = block * 64 + mt * 16 + (lane >> 2);
    const int r1 = r0 + 8;
    const int c0 = ks * 16 + (lane & 3) * 2;
    float2 v00 = make_float2(0.f, 0.f), v01 = v00, v10 = v00, v11 = v00;
    if (r0 < M) {
        v00 = *(const float2*)(A + (size_t)r0 * HN + c0);
        v01 = *(const float2*)(A + (size_t)r0 * HN + c0 + 8);
    }
    if (r1 < M) {
        v10 = *(const float2*)(A + (size_t)r1 * HN + c0);
        v11 = *(const float2*)(A + (size_t)r1 * HN + c0 + 8);
    }
    uint4 o;
    o.x = h2u(__floats2half2_rn(v00.x, v00.y));
    o.y = h2u(__floats2half2_rn(v10.x, v10.y));
    o.z = h2u(__floats2half2_rn(v01.x, v01.y));
    o.w = h2u(__floats2half2_rn(v11.x, v11.y));
    dst[gid] = o;
}

// B pack: gid = mode(1)|half(1)|ks(3)|wn(2)|nt(2)|lane(5); unit = uint2 (b0,b1)
// b0={W[k][n],W[k+1][n]}, b1={W[k+8][n],W[k+9][n]}; n=half*128+wn*32+nt*8+(lane>>2)
__global__ void prepW_kernel(const float* __restrict__ W1) {
    const int gid = blockIdx.x * blockDim.x + threadIdx.x;
    if (gid >= 16384) return;
    const int lane = gid & 31, nt = (gid >> 5) & 3, wn = (gid >> 7) & 3;
    const int ks = (gid >> 9) & 7, hf = (gid >> 12) & 1, mode = gid >> 13;
    const int n = hf * 128 + wn * 32 + nt * 8 + (lane >> 2);
    const int k = ks * 16 + (lane & 3) * 2 + mode * HN;
    uint2 o;
    o.x = h2u(__floats2half2_rn(W1[(size_t)k * FF + n], W1[(size_t)(k + 1) * FF + n]));
    o.y = h2u(__floats2half2_rn(W1[(size_t)(k + 8) * FF + n], W1[(size_t)(k + 9) * FF + n]));
    g_Wt16[mode][hf][gid & 4095] = o;
}

// ---------------- sync-free fp16 warp-mma GEMM ----------------
// MODE 0: g_P (fp32) = node_emb @ W_top + b1
// MODE 1: g_h16 (fp16) = edge_emb @ W_bot + g_P[i[row]]  (+ fused BN1 stats)
// Job j: tile=j>>1, half=j&1 (grid even => half==blockIdx.x&1 constant per CTA).
// 8 warps: wm=wid&1 (rows wm*64+[0,64)), wn=wid>>1 (local cols wn*32+[0,32)).
template <int MODE>
__global__ __launch_bounds__(256, 2) void mma_gemm(
    const uint4* __restrict__ Apk, const float* __restrict__ b1,
    const void* __restrict__ ibuf, void* __restrict__ outv, int M)
{
    __shared__ uint2 Bs[4096];
    __shared__ float sstat[256];

    const int tid = threadIdx.x, lane = tid & 31, wid = tid >> 5;
    const int wm = wid & 1, wn = wid >> 1;
    const int ntiles = (M + 127) >> 7;
    const long long njobs = (long long)ntiles * 2;
    const int G = gridDim.x;
    const int halfc = blockIdx.x & 1;
    const int is64 = (MODE == 1) ? g_is64 : 0;

    {   // B pack -> smem, once
        const uint4* src = (const uint4*)&g_Wt16[MODE][halfc][0];
        uint4* dstv = (uint4*)Bs;
        for (int i = tid; i < 2048; i += 256) dstv[i] = src[i];
    }
    if (MODE == 1) sstat[tid] = 0.f;
    __syncthreads();

    float acc[4][4][4];
#pragma unroll
    for (int mt = 0; mt < 4; mt++)
#pragma unroll
        for (int nt = 0; nt < 4; nt++)
#pragma unroll
            for (int r = 0; r < 4; r++) acc[mt][nt][r] = 0.f;

    for (long long job = blockIdx.x; job < njobs; job += G) {
        const long long tile = job >> 1;
        const uint4* abase = Apk + ((tile * 2 + wm) << 10);

        // ---- mainloop: no barriers, A double-buffered in regs ----
        uint4 acur[4], anxt[4];
#pragma unroll
        for (int mt = 0; mt < 4; mt++) acur[mt] = abase[mt * 32 + lane];
#pragma unroll
        for (int ks = 0; ks < 8; ks++) {
            uint2 bfr[4];
#pragma unroll
            for (int nt = 0; nt < 4; nt++)
                bfr[nt] = Bs[(ks * 16 + wn * 4 + nt) * 32 + lane];
            if (ks < 7) {
#pragma unroll
                for (int mt = 0; mt < 4; mt++)
                    anxt[mt] = abase[(ks + 1) * 128 + mt * 32 + lane];
            }
#pragma unroll
            for (int mt = 0; mt < 4; mt++)
#pragma unroll
                for (int nt = 0; nt < 4; nt++)
                    mma16(acc[mt][nt], acur[mt], bfr[nt]);
#pragma unroll
            for (int mt = 0; mt < 4; mt++) acur[mt] = anxt[mt];
        }

        // ---- epilogue ----
        const long long rbase = tile << 7;
        float s[4][2], q[4][2];
        if (MODE == 1) {
#pragma unroll
            for (int nt = 0; nt < 4; nt++) {
                s[nt][0] = s[nt][1] = 0.f; q[nt][0] = q[nt][1] = 0.f;
            }
        }
#pragma unroll
        for (int mt = 0; mt < 4; mt++) {
            long long pb[2]; bool valid[2]; long long rown[2];
#pragma unroll
            for (int h = 0; h < 2; h++) {
                const long long row = rbase + wm * 64 + mt * 16 + (lane >> 2) + h * 8;
                rown[h] = row;
                valid[h] = row < (long long)M;
                pb[h] = 0;
                if (MODE == 1 && valid[h]) {
                    const long long idx = is64 ? ((const long long*)ibuf)[row]
                                               : (long long)((const int*)ibuf)[row];
                    pb[h] = idx * FF;
                }
            }
#pragma unroll
            for (int nt = 0; nt < 4; nt++) {
                const int c0 = halfc * 128 + wn * 32 + nt * 8 + 2 * (lane & 3);
#pragma unroll
                for (int h = 0; h < 2; h++) {
                    if (!valid[h]) continue;
                    float2 add;
                    if (MODE == 0) add = *(const float2*)(b1 + c0);
                    else           add = *(const float2*)(g_P + pb[h] + c0);
                    float2 o;
                    o.x = acc[mt][nt][2 * h] + add.x;
                    o.y = acc[mt][nt][2 * h + 1] + add.y;
                    if (MODE == 0) {
                        *(float2*)((float*)outv + rown[h] * FF + c0) = o;
                    } else {
                        *(__half2*)((__half*)outv + rown[h] * FF + c0) =
                            __floats2half2_rn(o.x, o.y);
                        s[nt][0] += o.x; q[nt][0] = fmaf(o.x, o.x, q[nt][0]);
                        s[nt][1] += o.y; q[nt][1] = fmaf(o.y, o.y, q[nt][1]);
                    }
                }
                acc[mt][nt][0] = 0.f; acc[mt][nt][1] = 0.f;
                acc[mt][nt][2] = 0.f; acc[mt][nt][3] = 0.f;
            }
        }
        if (MODE == 1) {
#pragma unroll
            for (int o = 4; o < 32; o <<= 1) {
#pragma unroll
                for (int nt = 0; nt < 4; nt++) {
                    s[nt][0] += __shfl_xor_sync(0xffffffffu, s[nt][0], o);
                    s[nt][1] += __shfl_xor_sync(0xffffffffu, s[nt][1], o);
                    q[nt][0] += __shfl_xor_sync(0xffffffffu, q[nt][0], o);
                    q[nt][1] += __shfl_xor_sync(0xffffffffu, q[nt][1], o);
                }
            }
            if (lane < 4) {
#pragma unroll
                for (int nt = 0; nt < 4; nt++) {
                    const int lc = wn * 32 + nt * 8 + 2 * lane;
                    atomicAdd(&sstat[lc], s[nt][0]);
                    atomicAdd(&sstat[lc + 1], s[nt][1]);
                    atomicAdd(&sstat[128 + lc], q[nt][0]);
                    atomicAdd(&sstat[128 + lc + 1], q[nt][1]);
                }
            }
        }
    }
    if (MODE == 1) {
        __syncthreads();
        if (tid < 128) {
            atomicAdd(&g_stats1[halfc * 128 + tid], sstat[tid]);
            atomicAdd(&g_stats1[256 + halfc * 128 + tid], sstat[128 + tid]);
        }
    }
}

// ---------------- BN1 finalize ----------------
__global__ void finalize1_kernel(const float* __restrict__ gamma1,
                                 const float* __restrict__ beta1, float invE) {
    const int j = threadIdx.x;
    const float mu  = g_stats1[j] * invE;
    const float var = g_stats1[FF + j] * invE - mu * mu;
    const float s   = gamma1[j] * rsqrtf(var + EPS);
    g_scale[j] = s;
    g_shift[j] = beta1[j] - mu * s;
}

// ---------------- gate + scatter (fp16 h, vector atomics) ----------------
__global__ void gate_scatter_kernel(const void* __restrict__ ibuf, int E) {
    __shared__ float ssc[FF], ssh[FF];
    ssc[threadIdx.x] = g_scale[threadIdx.x];
    ssh[threadIdx.x] = g_shift[threadIdx.x];
    __syncthreads();
    const int is64 = g_is64;
    const long long total  = (long long)E * 32;
    const long long stride = (long long)gridDim.x * blockDim.x;
    for (long long t = (long long)blockIdx.x * blockDim.x + threadIdx.x;
         t < total; t += stride) {
        const long long e = t >> 5;
        const int c4 = (int)(t & 31) << 2;
        const __half* hrow = g_h16 + e * FF;
        const __half2 f01 = *(const __half2*)(hrow + c4);
        const __half2 f23 = *(const __half2*)(hrow + c4 + 2);
        const __half2 g01 = *(const __half2*)(hrow + HN + c4);
        const __half2 g23 = *(const __half2*)(hrow + HN + c4 + 2);
        const float2 fa = __half22float2(f01), fb = __half22float2(f23);
        const float2 ga = __half22float2(g01), gb = __half22float2(g23);
        float4 m;
        m.x = sigmoidf_(fa.x * ssc[c4 + 0] + ssh[c4 + 0]) * tanhf_(ga.x * ssc[HN + c4 + 0] + ssh[HN + c4 + 0]);
        m.y = sigmoidf_(fa.y * ssc[c4 + 1] + ssh[c4 + 1]) * tanhf_(ga.y * ssc[HN + c4 + 1] + ssh[HN + c4 + 1]);
        m.z = sigmoidf_(fb.x * ssc[c4 + 2] + ssh[c4 + 2]) * tanhf_(gb.x * ssc[HN + c4 + 2] + ssh[HN + c4 + 2]);
        m.w = sigmoidf_(fb.y * ssc[c4 + 3] + ssh[c4 + 3]) * tanhf_(gb.y * ssc[HN + c4 + 3] + ssh[HN + c4 + 3]);
        const long long idx = is64 ? ((const long long*)ibuf)[e]
                                   : (long long)((const int*)ibuf)[e];
        float* dst = g_agg + idx * HN + c4;
        asm volatile("red.global.add.v4.f32 [%0], {%1, %2, %3, %4};"
                     :: "l"(dst), "f"(m.x), "f"(m.y), "f"(m.z), "f"(m.w) : "memory");
    }
}

// ---------------- BN2 + final ----------------
__global__ void stats2_kernel(int N) {
    const int t = blockIdx.x * blockDim.x + threadIdx.x;
    const int col = t & (HN - 1);
    const int r0 = t >> 7;
    const int rs = (gridDim.x * blockDim.x) >> 7;
    float s = 0.f, sq = 0.f;
    for (long long r = r0; r < N; r += rs) {
        const float v = g_agg[r * HN + col];
        s += v; sq = fmaf(v, v, sq);
    }
    atomicAdd(&g_stats2[col], s);
    atomicAdd(&g_stats2[HN + col], sq);
}

__global__ void final_kernel(const float* __restrict__ node_emb,
                             const float* __restrict__ gamma2,
                             const float* __restrict__ beta2,
                             float* __restrict__ out, int total, float invN) {
    const int t = blockIdx.x * blockDim.x + threadIdx.x;
    if (t >= total) return;
    const int col = t & (HN - 1);
    const float mu  = g_stats2[col] * invN;
    const float var = g_stats2[HN + col] * invN - mu * mu;
    const float c1  = (g_agg[t] - mu) * rsqrtf(var + EPS) * gamma2[col] + beta2[col];
    out[t] = tanhf_(node_emb[t] + c1);
}

// ---------------- launch ----------------
extern "C" void kernel_launch(void* const* d_in, const int* in_sizes, int n_in,
                              void* d_out, int out_size) {
    const float* node_emb = (const float*)d_in[0];
    const float* edge_emb = (const float*)d_in[1];
    const void*  ibuf     = d_in[2];
    const float* W1       = (const float*)d_in[3];
    const float* b1       = (const float*)d_in[4];
    const float* gamma1   = (const float*)d_in[5];
    const float* beta1    = (const float*)d_in[6];
    const float* gamma2   = (const float*)d_in[7];
    const float* beta2    = (const float*)d_in[8];
    float* out = (float*)d_out;

    const int N = in_sizes[0] / HN;
    const int E = in_sizes[1] / HN;

    float*  g_P_ptr;  cudaGetSymbolAddress((void**)&g_P_ptr, g_P);
    __half* g_h_ptr;  cudaGetSymbolAddress((void**)&g_h_ptr, g_h16);
    uint4*  g_Ae_ptr; cudaGetSymbolAddress((void**)&g_Ae_ptr, g_Ae);
    uint4*  g_An_ptr; cudaGetSymbolAddress((void**)&g_An_ptr, g_An);

    detect_kernel<<<1, 32>>>((const unsigned*)ibuf);
    zero_kernel<<<4096, 256>>>(N * HN);
    prepW_kernel<<<64, 256>>>(W1);

    const int unitsN = NBLK_N * 1024;
    const int unitsE = NBLK_E * 1024;
    prepA_kernel<<<(unitsN + 255) / 256, 256>>>(node_emb, g_An_ptr, N, unitsN);
    prepA_kernel<<<(unitsE + 255) / 256, 256>>>(edge_emb, g_Ae_ptr, E, unitsE);

    mma_gemm<0><<<296, 256>>>(g_An_ptr, b1, ibuf, g_P_ptr, N);
    mma_gemm<1><<<296, 256>>>(g_Ae_ptr, b1, ibuf, g_h_ptr, E);

    finalize1_kernel<<<1, 256>>>(gamma1, beta1, 1.0f / (float)E);
    gate_scatter_kernel<<<8192, 256>>>(ibuf, E);

    stats2_kernel<<<1024, 256>>>(N);
    final_kernel<<<(N * HN + 255) / 256, 256>>>(node_emb, gamma2, beta2, out,
                                                N * HN, 1.0f / (float)N);
}